// round 10
// baseline (speedup 1.0000x reference)
#include <cuda_runtime.h>
#include <cuda_fp16.h>
#include <math.h>
#include <stdint.h>

#define T_TOK 4096
#define D_DIM 1024
#define E_NUM 8
#define H_DIM 2816
#define KC 64

__device__ int   g_cnt[E_NUM];
__device__ int   g_slot_tok[E_NUM * T_TOK];
__device__ float g_slot_w[E_NUM * T_TOK];
__device__ int   g_tok_slot[T_TOK * 2];
__device__ float g_down[(size_t)E_NUM * T_TOK * D_DIM];
__device__ __half g_xh[(size_t)T_TOK * D_DIM];
__device__ __half g_w1h[(size_t)E_NUM * D_DIM * H_DIM];
__device__ __half g_w3h[(size_t)E_NUM * D_DIM * H_DIM];
__device__ __half g_w2h[(size_t)E_NUM * H_DIM * D_DIM];
__device__ __half g_hh[(size_t)E_NUM * T_TOK * H_DIM];

// ---------------- helpers ----------------
__device__ __forceinline__ uint32_t smem_u32(const void* p){
    uint32_t a; asm("{ .reg .u64 t; cvta.to.shared.u64 t, %1; cvt.u32.u64 %0, t; }" : "=r"(a) : "l"(p)); return a;
}
__device__ __forceinline__ void mma16(float* c, const uint32_t* a, const uint32_t* b){
    asm volatile("mma.sync.aligned.m16n8k16.row.col.f32.f16.f16.f32 "
        "{%0,%1,%2,%3}, {%4,%5,%6,%7}, {%8,%9}, {%0,%1,%2,%3};"
        : "+f"(c[0]), "+f"(c[1]), "+f"(c[2]), "+f"(c[3])
        : "r"(a[0]), "r"(a[1]), "r"(a[2]), "r"(a[3]), "r"(b[0]), "r"(b[1]));
}
__device__ __forceinline__ void ldsm4(uint32_t* r, uint32_t addr){
    asm volatile("ldmatrix.sync.aligned.m8n8.x4.shared.b16 {%0,%1,%2,%3}, [%4];"
        : "=r"(r[0]), "=r"(r[1]), "=r"(r[2]), "=r"(r[3]) : "r"(addr));
}
__device__ __forceinline__ void ldsm4t(uint32_t* r, uint32_t addr){
    asm volatile("ldmatrix.sync.aligned.m8n8.x4.trans.shared.b16 {%0,%1,%2,%3}, [%4];"
        : "=r"(r[0]), "=r"(r[1]), "=r"(r[2]), "=r"(r[3]) : "r"(addr));
}
__device__ __forceinline__ float silu_mul(float g, float u){
    return (g / (1.f + expf(-g))) * u;
}
__device__ __forceinline__ void cpa16(uint32_t dst, const void* src){
    asm volatile("cp.async.cg.shared.global [%0], [%1], 16;" :: "r"(dst), "l"(src) : "memory");
}
#define CP_COMMIT() asm volatile("cp.async.commit_group;" ::: "memory")
#define CP_WAIT0()  asm volatile("cp.async.wait_group 0;" ::: "memory")

// ---------------- small kernels ----------------
__global__ void zero_cnt_kernel() { if (threadIdx.x < E_NUM) g_cnt[threadIdx.x] = 0; }

__global__ __launch_bounds__(256) void cvt_f16_kernel(const float* __restrict__ src,
                                                      __half* __restrict__ dst, int n8){
    const int i = blockIdx.x * 256 + threadIdx.x;
    if (i < n8) {
        const float4* s4 = (const float4*)src + 2 * (size_t)i;
        float4 a = s4[0], b = s4[1];
        half2 h0 = __floats2half2_rn(a.x, a.y);
        half2 h1 = __floats2half2_rn(a.z, a.w);
        half2 h2 = __floats2half2_rn(b.x, b.y);
        half2 h3 = __floats2half2_rn(b.z, b.w);
        uint4 o;
        o.x = *(uint32_t*)&h0; o.y = *(uint32_t*)&h1;
        o.z = *(uint32_t*)&h2; o.w = *(uint32_t*)&h3;
        *(uint4*)(dst + 8 * (size_t)i) = o;
    }
}

__global__ __launch_bounds__(256) void gating_kernel(const float* __restrict__ x,
                                                     const float* __restrict__ wg){
    __shared__ float s_red[E_NUM][256];
    const int t = blockIdx.x, tid = threadIdx.x;
    const float* xr = x + (size_t)t * D_DIM;
    float part[E_NUM];
#pragma unroll
    for (int e = 0; e < E_NUM; e++) part[e] = 0.f;
    for (int d = tid; d < D_DIM; d += 256) {
        const float xv = xr[d];
        const float* w = wg + (size_t)d * E_NUM;
#pragma unroll
        for (int e = 0; e < E_NUM; e++) part[e] += xv * w[e];
    }
#pragma unroll
    for (int e = 0; e < E_NUM; e++) s_red[e][tid] = part[e];
    __syncthreads();
    for (int s = 128; s > 0; s >>= 1) {
        if (tid < s) {
#pragma unroll
            for (int e = 0; e < E_NUM; e++) s_red[e][tid] += s_red[e][tid + s];
        }
        __syncthreads();
    }
    if (tid == 0) {
        float p[E_NUM]; float mx = -1e30f;
#pragma unroll
        for (int e = 0; e < E_NUM; e++) mx = fmaxf(mx, s_red[e][0]);
#pragma unroll
        for (int e = 0; e < E_NUM; e++) p[e] = expf(s_red[e][0] - mx);
        int i1 = 0;
#pragma unroll
        for (int e = 1; e < E_NUM; e++) if (p[e] > p[i1]) i1 = e;
        int i2 = (i1 == 0) ? 1 : 0;
#pragma unroll
        for (int e = 0; e < E_NUM; e++) if (e != i1 && p[e] > p[i2]) i2 = e;
        const float ws = p[i1] + p[i2];
        const int s0 = atomicAdd(&g_cnt[i1], 1);
        const int s1 = atomicAdd(&g_cnt[i2], 1);
        g_slot_tok[i1 * T_TOK + s0] = t;  g_slot_w[i1 * T_TOK + s0] = p[i1] / ws;
        g_slot_tok[i2 * T_TOK + s1] = t;  g_slot_w[i2 * T_TOK + s1] = p[i2] / ws;
        g_tok_slot[2 * t + 0] = i1 * T_TOK + s0;
        g_tok_slot[2 * t + 1] = i2 * T_TOK + s1;
    }
}

__global__ __launch_bounds__(256) void combine_kernel(float* __restrict__ out){
    const int t = blockIdx.x, i = threadIdx.x;
    const int s0 = g_tok_slot[2 * t + 0], s1 = g_tok_slot[2 * t + 1];
    const float4 a = *(const float4*)(g_down + (size_t)s0 * D_DIM + i * 4);
    const float4 b = *(const float4*)(g_down + (size_t)s1 * D_DIM + i * 4);
    float4 o; o.x = a.x + b.x; o.y = a.y + b.y; o.z = a.z + b.z; o.w = a.w + b.w;
    *(float4*)(out + (size_t)t * D_DIM + i * 4) = o;
}

// SMEM (bytes per buffer):
// gemm13: A[128][72]h (18432) | B1[64][40]h (5120) | B3[64][40]h (5120) = 28672
// gemm2 : A[128][72]h (18432) | B[64][72]h  (9216)                      = 27648
#define BUFB13  28672
#define B1OFFB  18432
#define B3OFFB  23552
#define BUFB2   27648
#define B2OFFB  18432

extern __shared__ uint32_t dyn[];

// ---------------- gemm13: h = silu(X@w1)*(X@w3). BM=128, BN=32/matrix, KC=64.
// 4 warps (2M x 2N), warp tile 64m x 16n per matrix. 2-stage cp.async, 3 CTAs/SM.
__global__ __launch_bounds__(128, 3) void gemm13_mma(){
    const int e = blockIdx.z, cnt = g_cnt[e], m0 = blockIdx.y * 128;
    if (m0 >= cnt) return;
    const int n0 = blockIdx.x * 32;

    __shared__ int s_row[128];
    const uint32_t sbase = smem_u32(dyn);
    const int tid = threadIdx.x, wid = tid >> 5, lane = tid & 31;
    const int gq = lane >> 2, tq = lane & 3;
    const int warp_m = (wid & 1) * 64, warp_n = (wid >> 1) * 16;

    s_row[tid] = g_slot_tok[e * T_TOK + min(m0 + tid, cnt - 1)];
    __syncthreads();

    const __half* xs = g_xh + (size_t)s_row[tid] * D_DIM;  // + kg
    const int brow = tid >> 1, bcol = (tid & 1) * 16;       // B: 64 rows x 32 halves
    const __half* w1s = g_w1h + ((size_t)e * D_DIM + brow) * H_DIM + n0 + bcol;
    const __half* w3s = g_w3h + ((size_t)e * D_DIM + brow) * H_DIM + n0 + bcol;
    const uint32_t dA  = sbase + (uint32_t)tid * 144u;
    const uint32_t dB1 = sbase + B1OFFB + (uint32_t)(brow * 80 + bcol * 2);
    const uint32_t dB3 = sbase + B3OFFB + (uint32_t)(brow * 80 + bcol * 2);

    auto fill = [&](int c){
        const uint32_t bo = (uint32_t)(c & 1) * BUFB13;
        const int kg = c * KC;
        const __half* pa = xs + kg;
#pragma unroll
        for (int i = 0; i < 8; i++) cpa16(dA + bo + i * 16, pa + i * 8);
        const __half* p1 = w1s + (size_t)kg * H_DIM;
        const __half* p3 = w3s + (size_t)kg * H_DIM;
        cpa16(dB1 + bo,      p1);
        cpa16(dB1 + bo + 16, p1 + 8);
        cpa16(dB3 + bo,      p3);
        cpa16(dB3 + bo + 16, p3 + 8);
    };

    uint32_t a_off[4];
#pragma unroll
    for (int i = 0; i < 4; i++)
        a_off[i] = (uint32_t)(((warp_m + i * 16 + (lane & 15)) * 72 + (lane >> 4) * 8) * 2);
    const uint32_t b1_off = (uint32_t)(B1OFFB + ((lane & 15) * 40 + warp_n + (lane >> 4) * 8) * 2);
    const uint32_t b3_off = (uint32_t)(B3OFFB + ((lane & 15) * 40 + warp_n + (lane >> 4) * 8) * 2);

    float accg[4][2][4], accu[4][2][4];
#pragma unroll
    for (int i = 0; i < 4; i++)
#pragma unroll
        for (int j = 0; j < 2; j++)
#pragma unroll
            for (int q = 0; q < 4; q++) { accg[i][j][q] = 0.f; accu[i][j][q] = 0.f; }

    const int NC = D_DIM / KC;  // 16
    fill(0); CP_COMMIT();

    for (int c = 0; c < NC; c++) {
        CP_WAIT0();
        __syncthreads();
        if (c + 1 < NC) fill(c + 1);
        CP_COMMIT();

        const uint32_t abuf = sbase + (uint32_t)(c & 1) * BUFB13;
        uint32_t af[2][4][4], b1f[2][2][2], b3f[2][2][2];

        auto ldfr = [&](int ks, int buf){
#pragma unroll
            for (int i = 0; i < 4; i++) ldsm4(af[buf][i], abuf + a_off[i] + ks * 32);
            uint32_t d[4];
            ldsm4t(d, abuf + b1_off + ks * 1280);
            b1f[buf][0][0] = d[0]; b1f[buf][0][1] = d[1];
            b1f[buf][1][0] = d[2]; b1f[buf][1][1] = d[3];
            ldsm4t(d, abuf + b3_off + ks * 1280);
            b3f[buf][0][0] = d[0]; b3f[buf][0][1] = d[1];
            b3f[buf][1][0] = d[2]; b3f[buf][1][1] = d[3];
        };
        ldfr(0, 0);
#pragma unroll
        for (int ks = 0; ks < 4; ks++) {
            const int cur = ks & 1, nxt = cur ^ 1;
            if (ks < 3) ldfr(ks + 1, nxt);
#pragma unroll
            for (int j = 0; j < 2; j++)
#pragma unroll
                for (int i = 0; i < 4; i++) {
                    mma16(accg[i][j], af[cur][i], b1f[cur][j]);
                    mma16(accu[i][j], af[cur][i], b3f[cur][j]);
                }
        }
    }

    __half* hb = g_hh + ((size_t)e * T_TOK + m0) * H_DIM + n0;
#pragma unroll
    for (int i = 0; i < 4; i++) {
        const int r0 = warp_m + i * 16 + gq;
        const int r1 = r0 + 8;
#pragma unroll
        for (int j = 0; j < 2; j++) {
            const int col = warp_n + j * 8 + tq * 2;
            if (m0 + r0 < cnt) {
                half2 o = __floats2half2_rn(silu_mul(accg[i][j][0], accu[i][j][0]),
                                            silu_mul(accg[i][j][1], accu[i][j][1]));
                *(half2*)(hb + (size_t)r0 * H_DIM + col) = o;
            }
            if (m0 + r1 < cnt) {
                half2 o = __floats2half2_rn(silu_mul(accg[i][j][2], accu[i][j][2]),
                                            silu_mul(accg[i][j][3], accu[i][j][3]));
                *(half2*)(hb + (size_t)r1 * H_DIM + col) = o;
            }
        }
    }
}

// ---------------- gemm2: down = w_m * (H @ w2). BM=128, BN=64, KC=64.
// 4 warps (2M x 2N), warp tile 64x32. 2-stage cp.async, 3 CTAs/SM.
__global__ __launch_bounds__(128, 3) void gemm2_mma(){
    const int e = blockIdx.z, cnt = g_cnt[e], m0 = blockIdx.y * 128;
    if (m0 >= cnt) return;
    const int n0 = blockIdx.x * 64;

    const uint32_t sbase = smem_u32(dyn);
    const int tid = threadIdx.x, wid = tid >> 5, lane = tid & 31;
    const int gq = lane >> 2, tq = lane & 3;
    const int warp_m = (wid & 1) * 64, warp_n = (wid >> 1) * 32;

    const __half* hs = g_hh + ((size_t)e * T_TOK + min(m0 + tid, cnt - 1)) * H_DIM;  // + kg
    const int brow = tid >> 1, bcol = (tid & 1) * 32;   // B: 64 rows x 64 halves
    const __half* w2s = g_w2h + ((size_t)e * H_DIM + brow) * D_DIM + n0 + bcol;
    const uint32_t dA = sbase + (uint32_t)tid * 144u;
    const uint32_t dB = sbase + B2OFFB + (uint32_t)(brow * 144 + bcol * 2);

    auto fill = [&](int c){
        const uint32_t bo = (uint32_t)(c & 1) * BUFB2;
        const int kg = c * KC;
        const __half* pa = hs + kg;
#pragma unroll
        for (int i = 0; i < 8; i++) cpa16(dA + bo + i * 16, pa + i * 8);
        const __half* pb = w2s + (size_t)kg * D_DIM;
#pragma unroll
        for (int i = 0; i < 4; i++) cpa16(dB + bo + i * 16, pb + i * 8);
    };

    uint32_t a_off[4];
#pragma unroll
    for (int i = 0; i < 4; i++)
        a_off[i] = (uint32_t)(((warp_m + i * 16 + (lane & 15)) * 72 + (lane >> 4) * 8) * 2);
    uint32_t b_off[2];
#pragma unroll
    for (int p = 0; p < 2; p++)
        b_off[p] = (uint32_t)(B2OFFB + ((lane & 15) * 72 + warp_n + p * 16 + (lane >> 4) * 8) * 2);

    float acc[4][4][4];
#pragma unroll
    for (int i = 0; i < 4; i++)
#pragma unroll
        for (int j = 0; j < 4; j++)
#pragma unroll
            for (int q = 0; q < 4; q++) acc[i][j][q] = 0.f;

    const int NC = H_DIM / KC;  // 44
    fill(0); CP_COMMIT();

    for (int c = 0; c < NC; c++) {
        CP_WAIT0();
        __syncthreads();
        if (c + 1 < NC) fill(c + 1);
        CP_COMMIT();

        const uint32_t abuf = sbase + (uint32_t)(c & 1) * BUFB2;
        uint32_t af[2][4][4], bf[2][4][2];

        auto ldfr = [&](int ks, int buf){
#pragma unroll
            for (int i = 0; i < 4; i++) ldsm4(af[buf][i], abuf + a_off[i] + ks * 32);
#pragma unroll
            for (int p = 0; p < 2; p++) {
                uint32_t d[4];
                ldsm4t(d, abuf + b_off[p] + ks * 2304);
                bf[buf][2*p][0] = d[0]; bf[buf][2*p][1] = d[1];
                bf[buf][2*p+1][0] = d[2]; bf[buf][2*p+1][1] = d[3];
            }
        };
        ldfr(0, 0);
#pragma unroll
        for (int ks = 0; ks < 4; ks++) {
            const int cur = ks & 1, nxt = cur ^ 1;
            if (ks < 3) ldfr(ks + 1, nxt);
#pragma unroll
            for (int j = 0; j < 4; j++)
#pragma unroll
                for (int i = 0; i < 4; i++) mma16(acc[i][j], af[cur][i], bf[cur][j]);
        }
    }

    float* db = g_down + ((size_t)e * T_TOK + m0) * D_DIM + n0;
#pragma unroll
    for (int i = 0; i < 4; i++) {
        const int r0 = warp_m + i * 16 + gq;
        const int r1 = r0 + 8;
        const float wg0 = g_slot_w[e * T_TOK + min(m0 + r0, cnt - 1)];
        const float wg1 = g_slot_w[e * T_TOK + min(m0 + r1, cnt - 1)];
#pragma unroll
        for (int j = 0; j < 4; j++) {
            const int col = warp_n + j * 8 + tq * 2;
            if (m0 + r0 < cnt) {
                float2 o; o.x = acc[i][j][0] * wg0; o.y = acc[i][j][1] * wg0;
                *(float2*)(db + (size_t)r0 * D_DIM + col) = o;
            }
            if (m0 + r1 < cnt) {
                float2 o; o.x = acc[i][j][2] * wg1; o.y = acc[i][j][3] * wg1;
                *(float2*)(db + (size_t)r1 * D_DIM + col) = o;
            }
        }
    }
}

// ---------------- launch ----------------
extern "C" void kernel_launch(void* const* d_in, const int* in_sizes, int n_in,
                              void* d_out, int out_size){
    const float* x  = (const float*)d_in[0];
    const float* wg = (const float*)d_in[1];
    const float* w1 = (const float*)d_in[2];
    const float* w2 = (const float*)d_in[3];
    const float* w3 = (const float*)d_in[4];
    float* out = (float*)d_out;

    const int smem13 = 2 * BUFB13;  // 57344
    const int smem2  = 2 * BUFB2;   // 55296
    cudaFuncSetAttribute(gemm13_mma, cudaFuncAttributeMaxDynamicSharedMemorySize, smem13);
    cudaFuncSetAttribute(gemm2_mma,  cudaFuncAttributeMaxDynamicSharedMemorySize, smem2);

    __half* xh;  cudaGetSymbolAddress((void**)&xh,  g_xh);
    __half* w1h; cudaGetSymbolAddress((void**)&w1h, g_w1h);
    __half* w3h; cudaGetSymbolAddress((void**)&w3h, g_w3h);
    __half* w2h; cudaGetSymbolAddress((void**)&w2h, g_w2h);

    const int nw8 = (E_NUM * D_DIM * H_DIM) / 8;
    const int nx8 = (T_TOK * D_DIM) / 8;

    zero_cnt_kernel<<<1, 32>>>();
    gating_kernel<<<T_TOK, 256>>>(x, wg);
    cvt_f16_kernel<<<(nx8 + 255) / 256, 256>>>(x,  xh,  nx8);
    cvt_f16_kernel<<<(nw8 + 255) / 256, 256>>>(w1, w1h, nw8);
    cvt_f16_kernel<<<(nw8 + 255) / 256, 256>>>(w3, w3h, nw8);
    cvt_f16_kernel<<<(nw8 + 255) / 256, 256>>>(w2, w2h, nw8);
    gemm13_mma<<<dim3(H_DIM / 32, T_TOK / 128, E_NUM), 128, smem13>>>();
    gemm2_mma<<<dim3(D_DIM / 64, T_TOK / 128, E_NUM), 128, smem2>>>();
    combine_kernel<<<T_TOK, 256>>>(out);
}

// round 11
// speedup vs baseline: 1.3321x; 1.3321x over previous
#include <cuda_runtime.h>
#include <cuda_fp16.h>
#include <math.h>
#include <stdint.h>

#define T_TOK 4096
#define D_DIM 1024
#define E_NUM 8
#define H_DIM 2816
#define KC 64

__device__ int   g_cnt[E_NUM];
__device__ int   g_slot_tok[E_NUM * T_TOK];
__device__ float g_slot_w[E_NUM * T_TOK];
__device__ int   g_tok_slot[T_TOK * 2];
__device__ float g_down[(size_t)E_NUM * T_TOK * D_DIM];
__device__ __half g_xh[(size_t)T_TOK * D_DIM];
__device__ __half g_w1h[(size_t)E_NUM * D_DIM * H_DIM];
__device__ __half g_w3h[(size_t)E_NUM * D_DIM * H_DIM];
__device__ __half g_w2h[(size_t)E_NUM * H_DIM * D_DIM];
__device__ __half g_hh[(size_t)E_NUM * T_TOK * H_DIM];

// ---------------- helpers ----------------
__device__ __forceinline__ uint32_t smem_u32(const void* p){
    uint32_t a; asm("{ .reg .u64 t; cvta.to.shared.u64 t, %1; cvt.u32.u64 %0, t; }" : "=r"(a) : "l"(p)); return a;
}
__device__ __forceinline__ void mma16(float* c, const uint32_t* a, const uint32_t* b){
    asm volatile("mma.sync.aligned.m16n8k16.row.col.f32.f16.f16.f32 "
        "{%0,%1,%2,%3}, {%4,%5,%6,%7}, {%8,%9}, {%0,%1,%2,%3};"
        : "+f"(c[0]), "+f"(c[1]), "+f"(c[2]), "+f"(c[3])
        : "r"(a[0]), "r"(a[1]), "r"(a[2]), "r"(a[3]), "r"(b[0]), "r"(b[1]));
}
__device__ __forceinline__ void ldsm4(uint32_t* r, uint32_t addr){
    asm volatile("ldmatrix.sync.aligned.m8n8.x4.shared.b16 {%0,%1,%2,%3}, [%4];"
        : "=r"(r[0]), "=r"(r[1]), "=r"(r[2]), "=r"(r[3]) : "r"(addr));
}
__device__ __forceinline__ void ldsm4t(uint32_t* r, uint32_t addr){
    asm volatile("ldmatrix.sync.aligned.m8n8.x4.trans.shared.b16 {%0,%1,%2,%3}, [%4];"
        : "=r"(r[0]), "=r"(r[1]), "=r"(r[2]), "=r"(r[3]) : "r"(addr));
}
__device__ __forceinline__ float silu_mul(float g, float u){
    return (g / (1.f + expf(-g))) * u;
}
__device__ __forceinline__ void cpa16(uint32_t dst, const void* src){
    asm volatile("cp.async.cg.shared.global [%0], [%1], 16;" :: "r"(dst), "l"(src) : "memory");
}
#define CP_COMMIT() asm volatile("cp.async.commit_group;" ::: "memory")
#define CP_WAIT1()  asm volatile("cp.async.wait_group 1;" ::: "memory")
#define CP_WAIT2()  asm volatile("cp.async.wait_group 2;" ::: "memory")

// ---------------- small kernels ----------------
__global__ void zero_cnt_kernel() { if (threadIdx.x < E_NUM) g_cnt[threadIdx.x] = 0; }

__global__ __launch_bounds__(256) void cvt_f16_kernel(const float* __restrict__ src,
                                                      __half* __restrict__ dst, int n8){
    const int i = blockIdx.x * 256 + threadIdx.x;
    if (i < n8) {
        const float4* s4 = (const float4*)src + 2 * (size_t)i;
        float4 a = s4[0], b = s4[1];
        half2 h0 = __floats2half2_rn(a.x, a.y);
        half2 h1 = __floats2half2_rn(a.z, a.w);
        half2 h2 = __floats2half2_rn(b.x, b.y);
        half2 h3 = __floats2half2_rn(b.z, b.w);
        uint4 o;
        o.x = *(uint32_t*)&h0; o.y = *(uint32_t*)&h1;
        o.z = *(uint32_t*)&h2; o.w = *(uint32_t*)&h3;
        *(uint4*)(dst + 8 * (size_t)i) = o;
    }
}

__global__ __launch_bounds__(256) void gating_kernel(const float* __restrict__ x,
                                                     const float* __restrict__ wg){
    __shared__ float s_red[E_NUM][256];
    const int t = blockIdx.x, tid = threadIdx.x;
    const float* xr = x + (size_t)t * D_DIM;
    float part[E_NUM];
#pragma unroll
    for (int e = 0; e < E_NUM; e++) part[e] = 0.f;
    for (int d = tid; d < D_DIM; d += 256) {
        const float xv = xr[d];
        const float* w = wg + (size_t)d * E_NUM;
#pragma unroll
        for (int e = 0; e < E_NUM; e++) part[e] += xv * w[e];
    }
#pragma unroll
    for (int e = 0; e < E_NUM; e++) s_red[e][tid] = part[e];
    __syncthreads();
    for (int s = 128; s > 0; s >>= 1) {
        if (tid < s) {
#pragma unroll
            for (int e = 0; e < E_NUM; e++) s_red[e][tid] += s_red[e][tid + s];
        }
        __syncthreads();
    }
    if (tid == 0) {
        float p[E_NUM]; float mx = -1e30f;
#pragma unroll
        for (int e = 0; e < E_NUM; e++) mx = fmaxf(mx, s_red[e][0]);
#pragma unroll
        for (int e = 0; e < E_NUM; e++) p[e] = expf(s_red[e][0] - mx);
        int i1 = 0;
#pragma unroll
        for (int e = 1; e < E_NUM; e++) if (p[e] > p[i1]) i1 = e;
        int i2 = (i1 == 0) ? 1 : 0;
#pragma unroll
        for (int e = 0; e < E_NUM; e++) if (e != i1 && p[e] > p[i2]) i2 = e;
        const float ws = p[i1] + p[i2];
        const int s0 = atomicAdd(&g_cnt[i1], 1);
        const int s1 = atomicAdd(&g_cnt[i2], 1);
        g_slot_tok[i1 * T_TOK + s0] = t;  g_slot_w[i1 * T_TOK + s0] = p[i1] / ws;
        g_slot_tok[i2 * T_TOK + s1] = t;  g_slot_w[i2 * T_TOK + s1] = p[i2] / ws;
        g_tok_slot[2 * t + 0] = i1 * T_TOK + s0;
        g_tok_slot[2 * t + 1] = i2 * T_TOK + s1;
    }
}

__global__ __launch_bounds__(256) void combine_kernel(float* __restrict__ out){
    const int t = blockIdx.x, i = threadIdx.x;
    const int s0 = g_tok_slot[2 * t + 0], s1 = g_tok_slot[2 * t + 1];
    const float4 a = *(const float4*)(g_down + (size_t)s0 * D_DIM + i * 4);
    const float4 b = *(const float4*)(g_down + (size_t)s1 * D_DIM + i * 4);
    float4 o; o.x = a.x + b.x; o.y = a.y + b.y; o.z = a.z + b.z; o.w = a.w + b.w;
    *(float4*)(out + (size_t)t * D_DIM + i * 4) = o;
}

// SMEM layouts in halves. A[128][72] rows pitch 144B (bank step 4, conflict-free ldsm).
// gemm13: A(9216) | B1[64][72](4608) | B3[64][72](4608) -> 18432 halves = 36864 B/buf, 3 stages
// gemm2 : A(9216) | B[64][136](8704)                     -> 17920 halves = 35840 B/buf, 4 stages
#define BUFB13 36864
#define B1OFFB 18432
#define B3OFFB 27648
#define BUFB2  35840
#define B2OFFB 18432

extern __shared__ uint32_t dyn[];

// ---------------- gemm13: h = silu(X@w1)*(X@w3). BM=128,BN=64/matrix,KC=64.
// 4 warps (2M x 2N), warp tile 64m x 32n per matrix. 3-stage cp.async pipeline.
__global__ __launch_bounds__(128, 2) void gemm13_mma(){
    const int e = blockIdx.z, cnt = g_cnt[e], m0 = blockIdx.y * 128;
    if (m0 >= cnt) return;
    const int n0 = blockIdx.x * 64;

    __shared__ int s_row[128];
    const uint32_t sbase = smem_u32(dyn);
    const int tid = threadIdx.x, wid = tid >> 5, lane = tid & 31;
    const int gq = lane >> 2, tq = lane & 3;
    const int warp_m = (wid & 1) * 64, warp_n = (wid >> 1) * 32;

    s_row[tid] = g_slot_tok[e * T_TOK + min(m0 + tid, cnt - 1)];
    __syncthreads();

    const __half* xs  = g_xh + (size_t)s_row[tid] * D_DIM;            // + kg
    const int brow = tid >> 1, bhw = (tid & 1) * 32;
    const __half* w1s = g_w1h + ((size_t)e * D_DIM + brow) * H_DIM + n0 + bhw;  // + kg*H
    const __half* w3s = g_w3h + ((size_t)e * D_DIM + brow) * H_DIM + n0 + bhw;
    const uint32_t dA  = sbase + (uint32_t)tid * 144u;
    const uint32_t dB1 = sbase + B1OFFB + (uint32_t)(brow * 144 + bhw * 2);
    const uint32_t dB3 = sbase + B3OFFB + (uint32_t)(brow * 144 + bhw * 2);

    auto fill = [&](int c){
        const uint32_t bo = (uint32_t)(c % 3) * BUFB13;
        const int kg = c * KC;
        const __half* pa = xs + kg;
#pragma unroll
        for (int i = 0; i < 8; i++) cpa16(dA + bo + i * 16, pa + i * 8);
        const __half* p1 = w1s + (size_t)kg * H_DIM;
        const __half* p3 = w3s + (size_t)kg * H_DIM;
#pragma unroll
        for (int i = 0; i < 4; i++) cpa16(dB1 + bo + i * 16, p1 + i * 8);
#pragma unroll
        for (int i = 0; i < 4; i++) cpa16(dB3 + bo + i * 16, p3 + i * 8);
    };

    // ldmatrix lane offsets (bytes)
    uint32_t a_off[4];
#pragma unroll
    for (int i = 0; i < 4; i++)
        a_off[i] = (uint32_t)(((warp_m + i * 16 + (lane & 15)) * 72 + (lane >> 4) * 8) * 2);
    uint32_t b_off[2];
#pragma unroll
    for (int p = 0; p < 2; p++)
        b_off[p] = (uint32_t)(B1OFFB + ((lane & 15) * 72 + warp_n + p * 16 + (lane >> 4) * 8) * 2);

    float accg[4][4][4], accu[4][4][4];
#pragma unroll
    for (int i = 0; i < 4; i++)
#pragma unroll
        for (int j = 0; j < 4; j++)
#pragma unroll
            for (int q = 0; q < 4; q++) { accg[i][j][q] = 0.f; accu[i][j][q] = 0.f; }

    const int NC = D_DIM / KC;  // 16
    fill(0); CP_COMMIT();
    fill(1); CP_COMMIT();

    for (int c = 0; c < NC; c++) {
        CP_WAIT1();
        __syncthreads();
        if (c + 2 < NC) fill(c + 2);
        CP_COMMIT();

        const uint32_t abuf = sbase + (uint32_t)(c % 3) * BUFB13;
        uint32_t af[2][4][4], b1f[2][4][2], b3f[2][4][2];

        auto ldfr = [&](int ks, int buf){
#pragma unroll
            for (int i = 0; i < 4; i++) ldsm4(af[buf][i], abuf + a_off[i] + ks * 32);
#pragma unroll
            for (int p = 0; p < 2; p++) {
                uint32_t d[4];
                ldsm4t(d, abuf + b_off[p] + ks * 2304);
                b1f[buf][2*p][0] = d[0]; b1f[buf][2*p][1] = d[1];
                b1f[buf][2*p+1][0] = d[2]; b1f[buf][2*p+1][1] = d[3];
                ldsm4t(d, abuf + b_off[p] + 9216 + ks * 2304);
                b3f[buf][2*p][0] = d[0]; b3f[buf][2*p][1] = d[1];
                b3f[buf][2*p+1][0] = d[2]; b3f[buf][2*p+1][1] = d[3];
            }
        };
        ldfr(0, 0);
#pragma unroll
        for (int ks = 0; ks < 4; ks++) {
            const int cur = ks & 1, nxt = cur ^ 1;
            if (ks < 3) ldfr(ks + 1, nxt);
#pragma unroll
            for (int j = 0; j < 4; j++)
#pragma unroll
                for (int i = 0; i < 4; i++) {
                    mma16(accg[i][j], af[cur][i], b1f[cur][j]);
                    mma16(accu[i][j], af[cur][i], b3f[cur][j]);
                }
        }
    }

    __half* hb = g_hh + ((size_t)e * T_TOK + m0) * H_DIM + n0;
#pragma unroll
    for (int i = 0; i < 4; i++) {
        const int r0 = warp_m + i * 16 + gq;
        const int r1 = r0 + 8;
#pragma unroll
        for (int j = 0; j < 4; j++) {
            const int col = warp_n + j * 8 + tq * 2;
            if (m0 + r0 < cnt) {
                half2 o = __floats2half2_rn(silu_mul(accg[i][j][0], accu[i][j][0]),
                                            silu_mul(accg[i][j][1], accu[i][j][1]));
                *(half2*)(hb + (size_t)r0 * H_DIM + col) = o;
            }
            if (m0 + r1 < cnt) {
                half2 o = __floats2half2_rn(silu_mul(accg[i][j][2], accu[i][j][2]),
                                            silu_mul(accg[i][j][3], accu[i][j][3]));
                *(half2*)(hb + (size_t)r1 * H_DIM + col) = o;
            }
        }
    }
}

// ---------------- gemm2: down = w_m * (H @ w2). BM=128,BN=128,KC=64. warp 64x64.
// 4-stage cp.async pipeline (wait_group 2): double the boundary latency slack.
__global__ __launch_bounds__(128, 2) void gemm2_mma(){
    const int e = blockIdx.z, cnt = g_cnt[e], m0 = blockIdx.y * 128;
    if (m0 >= cnt) return;
    const int n0 = blockIdx.x * 128;

    const uint32_t sbase = smem_u32(dyn);
    const int tid = threadIdx.x, wid = tid >> 5, lane = tid & 31;
    const int gq = lane >> 2, tq = lane & 3;
    const int warp_m = (wid & 1) * 64, warp_n = (wid >> 1) * 64;

    const __half* hs = g_hh + ((size_t)e * T_TOK + min(m0 + tid, cnt - 1)) * H_DIM;  // + kg
    const int brow = tid >> 1, bhw = (tid & 1) * 64;
    const __half* w2s = g_w2h + ((size_t)e * H_DIM + brow) * D_DIM + n0 + bhw;       // + kg*D
    const uint32_t dA = sbase + (uint32_t)tid * 144u;
    const uint32_t dB = sbase + B2OFFB + (uint32_t)(brow * 272 + bhw * 2);

    auto fill = [&](int c){
        const uint32_t bo = (uint32_t)(c & 3) * BUFB2;
        const int kg = c * KC;
        const __half* pa = hs + kg;
#pragma unroll
        for (int i = 0; i < 8; i++) cpa16(dA + bo + i * 16, pa + i * 8);
        const __half* pb = w2s + (size_t)kg * D_DIM;
#pragma unroll
        for (int i = 0; i < 8; i++) cpa16(dB + bo + i * 16, pb + i * 8);
    };

    uint32_t a_off[4];
#pragma unroll
    for (int i = 0; i < 4; i++)
        a_off[i] = (uint32_t)(((warp_m + i * 16 + (lane & 15)) * 72 + (lane >> 4) * 8) * 2);
    uint32_t b_off[4];
#pragma unroll
    for (int p = 0; p < 4; p++)
        b_off[p] = (uint32_t)(B2OFFB + ((lane & 15) * 136 + warp_n + p * 16 + (lane >> 4) * 8) * 2);

    float acc[4][8][4];
#pragma unroll
    for (int i = 0; i < 4; i++)
#pragma unroll
        for (int j = 0; j < 8; j++)
#pragma unroll
            for (int q = 0; q < 4; q++) acc[i][j][q] = 0.f;

    const int NC = H_DIM / KC;  // 44
    fill(0); CP_COMMIT();
    fill(1); CP_COMMIT();
    fill(2); CP_COMMIT();

    for (int c = 0; c < NC; c++) {
        CP_WAIT2();
        __syncthreads();
        if (c + 3 < NC) fill(c + 3);
        CP_COMMIT();

        const uint32_t abuf = sbase + (uint32_t)(c & 3) * BUFB2;
        uint32_t af[2][4][4], bf[2][8][2];

        auto ldfr = [&](int ks, int buf){
#pragma unroll
            for (int i = 0; i < 4; i++) ldsm4(af[buf][i], abuf + a_off[i] + ks * 32);
#pragma unroll
            for (int p = 0; p < 4; p++) {
                uint32_t d[4];
                ldsm4t(d, abuf + b_off[p] + ks * 4352);
                bf[buf][2*p][0] = d[0]; bf[buf][2*p][1] = d[1];
                bf[buf][2*p+1][0] = d[2]; bf[buf][2*p+1][1] = d[3];
            }
        };
        ldfr(0, 0);
#pragma unroll
        for (int ks = 0; ks < 4; ks++) {
            const int cur = ks & 1, nxt = cur ^ 1;
            if (ks < 3) ldfr(ks + 1, nxt);
#pragma unroll
            for (int j = 0; j < 8; j++)
#pragma unroll
                for (int i = 0; i < 4; i++) mma16(acc[i][j], af[cur][i], bf[cur][j]);
        }
    }

    float* db = g_down + ((size_t)e * T_TOK + m0) * D_DIM + n0;
#pragma unroll
    for (int i = 0; i < 4; i++) {
        const int r0 = warp_m + i * 16 + gq;
        const int r1 = r0 + 8;
        const float wg0 = g_slot_w[e * T_TOK + min(m0 + r0, cnt - 1)];
        const float wg1 = g_slot_w[e * T_TOK + min(m0 + r1, cnt - 1)];
#pragma unroll
        for (int j = 0; j < 8; j++) {
            const int col = warp_n + j * 8 + tq * 2;
            if (m0 + r0 < cnt) {
                float2 o; o.x = acc[i][j][0] * wg0; o.y = acc[i][j][1] * wg0;
                *(float2*)(db + (size_t)r0 * D_DIM + col) = o;
            }
            if (m0 + r1 < cnt) {
                float2 o; o.x = acc[i][j][2] * wg1; o.y = acc[i][j][3] * wg1;
                *(float2*)(db + (size_t)r1 * D_DIM + col) = o;
            }
        }
    }
}

// ---------------- launch ----------------
extern "C" void kernel_launch(void* const* d_in, const int* in_sizes, int n_in,
                              void* d_out, int out_size){
    const float* x  = (const float*)d_in[0];
    const float* wg = (const float*)d_in[1];
    const float* w1 = (const float*)d_in[2];
    const float* w2 = (const float*)d_in[3];
    const float* w3 = (const float*)d_in[4];
    float* out = (float*)d_out;

    const int smem13 = 3 * BUFB13;  // 110592
    const int smem2  = 4 * BUFB2;   // 143360
    cudaFuncSetAttribute(gemm13_mma, cudaFuncAttributeMaxDynamicSharedMemorySize, smem13);
    cudaFuncSetAttribute(gemm2_mma,  cudaFuncAttributeMaxDynamicSharedMemorySize, smem2);

    __half* xh;  cudaGetSymbolAddress((void**)&xh,  g_xh);
    __half* w1h; cudaGetSymbolAddress((void**)&w1h, g_w1h);
    __half* w3h; cudaGetSymbolAddress((void**)&w3h, g_w3h);
    __half* w2h; cudaGetSymbolAddress((void**)&w2h, g_w2h);

    const int nw8 = (E_NUM * D_DIM * H_DIM) / 8;
    const int nx8 = (T_TOK * D_DIM) / 8;

    zero_cnt_kernel<<<1, 32>>>();
    gating_kernel<<<T_TOK, 256>>>(x, wg);
    cvt_f16_kernel<<<(nx8 + 255) / 256, 256>>>(x,  xh,  nx8);
    cvt_f16_kernel<<<(nw8 + 255) / 256, 256>>>(w1, w1h, nw8);
    cvt_f16_kernel<<<(nw8 + 255) / 256, 256>>>(w3, w3h, nw8);
    cvt_f16_kernel<<<(nw8 + 255) / 256, 256>>>(w2, w2h, nw8);
    gemm13_mma<<<dim3(H_DIM / 64, T_TOK / 128, E_NUM), 128, smem13>>>();
    gemm2_mma<<<dim3(D_DIM / 128, T_TOK / 128, E_NUM), 128, smem2>>>();
    combine_kernel<<<T_TOK, 256>>>(out);
}

// round 12
// speedup vs baseline: 1.3930x; 1.0457x over previous
#include <cuda_runtime.h>
#include <cuda_fp16.h>
#include <math.h>
#include <stdint.h>

#define T_TOK 4096
#define D_DIM 1024
#define E_NUM 8
#define H_DIM 2816
#define KC 64

__device__ int   g_cnt[E_NUM];
__device__ int   g_slot_tok[E_NUM * T_TOK];
__device__ float g_slot_w[E_NUM * T_TOK];
__device__ int   g_tok_slot[T_TOK * 2];
__device__ float g_down[(size_t)E_NUM * T_TOK * D_DIM];
__device__ __half g_xh[(size_t)T_TOK * D_DIM];
__device__ __half g_w1h[(size_t)E_NUM * D_DIM * H_DIM];
__device__ __half g_w3h[(size_t)E_NUM * D_DIM * H_DIM];
__device__ __half g_w2h[(size_t)E_NUM * H_DIM * D_DIM];
__device__ __half g_hh[(size_t)E_NUM * T_TOK * H_DIM];

// ---------------- helpers ----------------
__device__ __forceinline__ uint32_t smem_u32(const void* p){
    uint32_t a; asm("{ .reg .u64 t; cvta.to.shared.u64 t, %1; cvt.u32.u64 %0, t; }" : "=r"(a) : "l"(p)); return a;
}
__device__ __forceinline__ void mma16(float* c, const uint32_t* a, const uint32_t* b){
    asm volatile("mma.sync.aligned.m16n8k16.row.col.f32.f16.f16.f32 "
        "{%0,%1,%2,%3}, {%4,%5,%6,%7}, {%8,%9}, {%0,%1,%2,%3};"
        : "+f"(c[0]), "+f"(c[1]), "+f"(c[2]), "+f"(c[3])
        : "r"(a[0]), "r"(a[1]), "r"(a[2]), "r"(a[3]), "r"(b[0]), "r"(b[1]));
}
__device__ __forceinline__ void ldsm4(uint32_t* r, uint32_t addr){
    asm volatile("ldmatrix.sync.aligned.m8n8.x4.shared.b16 {%0,%1,%2,%3}, [%4];"
        : "=r"(r[0]), "=r"(r[1]), "=r"(r[2]), "=r"(r[3]) : "r"(addr));
}
__device__ __forceinline__ void ldsm4t(uint32_t* r, uint32_t addr){
    asm volatile("ldmatrix.sync.aligned.m8n8.x4.trans.shared.b16 {%0,%1,%2,%3}, [%4];"
        : "=r"(r[0]), "=r"(r[1]), "=r"(r[2]), "=r"(r[3]) : "r"(addr));
}
__device__ __forceinline__ float silu_mul(float g, float u){
    return (g / (1.f + expf(-g))) * u;
}
__device__ __forceinline__ void cpa16(uint32_t dst, const void* src){
    asm volatile("cp.async.cg.shared.global [%0], [%1], 16;" :: "r"(dst), "l"(src) : "memory");
}
#define CP_COMMIT() asm volatile("cp.async.commit_group;" ::: "memory")
#define CP_WAIT1()  asm volatile("cp.async.wait_group 1;" ::: "memory")

// ---------------- small kernels ----------------
__global__ void zero_cnt_kernel() { if (threadIdx.x < E_NUM) g_cnt[threadIdx.x] = 0; }

// fused fp32 -> fp16 pre-round over x, w1, w3, w2 (8 elements/thread)
__global__ __launch_bounds__(256) void cvt_all_kernel(const float* __restrict__ x,
                                                      const float* __restrict__ w1,
                                                      const float* __restrict__ w3,
                                                      const float* __restrict__ w2,
                                                      __half* __restrict__ xh,
                                                      __half* __restrict__ w1h,
                                                      __half* __restrict__ w3h,
                                                      __half* __restrict__ w2h){
    const int nx8 = (T_TOK * D_DIM) / 8;
    const int nw8 = (E_NUM * D_DIM * H_DIM) / 8;
    const int i = blockIdx.x * 256 + threadIdx.x;
    const float* src; __half* dst; size_t off;
    if (i < nx8) { src = x; dst = xh; off = (size_t)i; }
    else {
        const int j = i - nx8;
        const int arr = j / nw8;
        off = (size_t)(j - arr * nw8);
        if (arr == 0)      { src = w1; dst = w1h; }
        else if (arr == 1) { src = w3; dst = w3h; }
        else if (arr == 2) { src = w2; dst = w2h; }
        else return;
    }
    const float4* s4 = (const float4*)src + 2 * off;
    float4 a = s4[0], b = s4[1];
    half2 h0 = __floats2half2_rn(a.x, a.y);
    half2 h1 = __floats2half2_rn(a.z, a.w);
    half2 h2 = __floats2half2_rn(b.x, b.y);
    half2 h3 = __floats2half2_rn(b.z, b.w);
    uint4 o;
    o.x = *(uint32_t*)&h0; o.y = *(uint32_t*)&h1;
    o.z = *(uint32_t*)&h2; o.w = *(uint32_t*)&h3;
    *(uint4*)(dst + 8 * off) = o;
}

__global__ __launch_bounds__(256) void gating_kernel(const float* __restrict__ x,
                                                     const float* __restrict__ wg){
    __shared__ float s_red[E_NUM][256];
    const int t = blockIdx.x, tid = threadIdx.x;
    const float* xr = x + (size_t)t * D_DIM;
    float part[E_NUM];
#pragma unroll
    for (int e = 0; e < E_NUM; e++) part[e] = 0.f;
    for (int d = tid; d < D_DIM; d += 256) {
        const float xv = xr[d];
        const float* w = wg + (size_t)d * E_NUM;
#pragma unroll
        for (int e = 0; e < E_NUM; e++) part[e] += xv * w[e];
    }
#pragma unroll
    for (int e = 0; e < E_NUM; e++) s_red[e][tid] = part[e];
    __syncthreads();
    for (int s = 128; s > 0; s >>= 1) {
        if (tid < s) {
#pragma unroll
            for (int e = 0; e < E_NUM; e++) s_red[e][tid] += s_red[e][tid + s];
        }
        __syncthreads();
    }
    if (tid == 0) {
        float p[E_NUM]; float mx = -1e30f;
#pragma unroll
        for (int e = 0; e < E_NUM; e++) mx = fmaxf(mx, s_red[e][0]);
#pragma unroll
        for (int e = 0; e < E_NUM; e++) p[e] = expf(s_red[e][0] - mx);
        int i1 = 0;
#pragma unroll
        for (int e = 1; e < E_NUM; e++) if (p[e] > p[i1]) i1 = e;
        int i2 = (i1 == 0) ? 1 : 0;
#pragma unroll
        for (int e = 0; e < E_NUM; e++) if (e != i1 && p[e] > p[i2]) i2 = e;
        const float ws = p[i1] + p[i2];
        const int s0 = atomicAdd(&g_cnt[i1], 1);
        const int s1 = atomicAdd(&g_cnt[i2], 1);
        g_slot_tok[i1 * T_TOK + s0] = t;  g_slot_w[i1 * T_TOK + s0] = p[i1] / ws;
        g_slot_tok[i2 * T_TOK + s1] = t;  g_slot_w[i2 * T_TOK + s1] = p[i2] / ws;
        g_tok_slot[2 * t + 0] = i1 * T_TOK + s0;
        g_tok_slot[2 * t + 1] = i2 * T_TOK + s1;
    }
}

__global__ __launch_bounds__(256) void combine_kernel(float* __restrict__ out){
    const int t = blockIdx.x, i = threadIdx.x;
    const int s0 = g_tok_slot[2 * t + 0], s1 = g_tok_slot[2 * t + 1];
    const float4 a = *(const float4*)(g_down + (size_t)s0 * D_DIM + i * 4);
    const float4 b = *(const float4*)(g_down + (size_t)s1 * D_DIM + i * 4);
    float4 o; o.x = a.x + b.x; o.y = a.y + b.y; o.z = a.z + b.z; o.w = a.w + b.w;
    *(float4*)(out + (size_t)t * D_DIM + i * 4) = o;
}

// SMEM layouts in halves. A[128][72] rows pitch 144B (bank step 4, conflict-free ldsm).
// gemm13: A(9216) | B1[64][72](4608) | B3[64][72](4608) -> 18432 halves = 36864 B/buf, 3 stages
// gemm2 : A(9216) | B[64][136](8704)                     -> 17920 halves = 35840 B/buf, 3 stages
#define BUFB13 36864
#define B1OFFB 18432
#define B3OFFB 27648
#define BUFB2  35840
#define B2OFFB 18432

extern __shared__ uint32_t dyn[];

// ---------------- gemm13: h = silu(X@w1)*(X@w3). BM=128,BN=64/matrix,KC=64.
// 4 warps (2M x 2N), warp tile 64m x 32n per matrix. 3-stage cp.async pipeline.
__global__ __launch_bounds__(128, 2) void gemm13_mma(){
    const int e = blockIdx.z, cnt = g_cnt[e], m0 = blockIdx.y * 128;
    if (m0 >= cnt) return;
    const int n0 = blockIdx.x * 64;

    __shared__ int s_row[128];
    const uint32_t sbase = smem_u32(dyn);
    const int tid = threadIdx.x, wid = tid >> 5, lane = tid & 31;
    const int gq = lane >> 2, tq = lane & 3;
    const int warp_m = (wid & 1) * 64, warp_n = (wid >> 1) * 32;

    s_row[tid] = g_slot_tok[e * T_TOK + min(m0 + tid, cnt - 1)];
    __syncthreads();

    const __half* xs  = g_xh + (size_t)s_row[tid] * D_DIM;            // + kg
    const int brow = tid >> 1, bhw = (tid & 1) * 32;
    const __half* w1s = g_w1h + ((size_t)e * D_DIM + brow) * H_DIM + n0 + bhw;  // + kg*H
    const __half* w3s = g_w3h + ((size_t)e * D_DIM + brow) * H_DIM + n0 + bhw;
    const uint32_t dA  = sbase + (uint32_t)tid * 144u;
    const uint32_t dB1 = sbase + B1OFFB + (uint32_t)(brow * 144 + bhw * 2);
    const uint32_t dB3 = sbase + B3OFFB + (uint32_t)(brow * 144 + bhw * 2);

    auto fill = [&](int c){
        const uint32_t bo = (uint32_t)(c % 3) * BUFB13;
        const int kg = c * KC;
        const __half* pa = xs + kg;
#pragma unroll
        for (int i = 0; i < 8; i++) cpa16(dA + bo + i * 16, pa + i * 8);
        const __half* p1 = w1s + (size_t)kg * H_DIM;
        const __half* p3 = w3s + (size_t)kg * H_DIM;
#pragma unroll
        for (int i = 0; i < 4; i++) cpa16(dB1 + bo + i * 16, p1 + i * 8);
#pragma unroll
        for (int i = 0; i < 4; i++) cpa16(dB3 + bo + i * 16, p3 + i * 8);
    };

    // ldmatrix lane offsets (bytes)
    uint32_t a_off[4];
#pragma unroll
    for (int i = 0; i < 4; i++)
        a_off[i] = (uint32_t)(((warp_m + i * 16 + (lane & 15)) * 72 + (lane >> 4) * 8) * 2);
    uint32_t b_off[2];
#pragma unroll
    for (int p = 0; p < 2; p++)
        b_off[p] = (uint32_t)(B1OFFB + ((lane & 15) * 72 + warp_n + p * 16 + (lane >> 4) * 8) * 2);

    float accg[4][4][4], accu[4][4][4];
#pragma unroll
    for (int i = 0; i < 4; i++)
#pragma unroll
        for (int j = 0; j < 4; j++)
#pragma unroll
            for (int q = 0; q < 4; q++) { accg[i][j][q] = 0.f; accu[i][j][q] = 0.f; }

    const int NC = D_DIM / KC;  // 16
    fill(0); CP_COMMIT();
    fill(1); CP_COMMIT();

    for (int c = 0; c < NC; c++) {
        CP_WAIT1();
        __syncthreads();
        if (c + 2 < NC) fill(c + 2);
        CP_COMMIT();

        const uint32_t abuf = sbase + (uint32_t)(c % 3) * BUFB13;
        uint32_t af[2][4][4], b1f[2][4][2], b3f[2][4][2];

        auto ldfr = [&](int ks, int buf){
#pragma unroll
            for (int i = 0; i < 4; i++) ldsm4(af[buf][i], abuf + a_off[i] + ks * 32);
#pragma unroll
            for (int p = 0; p < 2; p++) {
                uint32_t d[4];
                ldsm4t(d, abuf + b_off[p] + ks * 2304);
                b1f[buf][2*p][0] = d[0]; b1f[buf][2*p][1] = d[1];
                b1f[buf][2*p+1][0] = d[2]; b1f[buf][2*p+1][1] = d[3];
                ldsm4t(d, abuf + b_off[p] + 9216 + ks * 2304);
                b3f[buf][2*p][0] = d[0]; b3f[buf][2*p][1] = d[1];
                b3f[buf][2*p+1][0] = d[2]; b3f[buf][2*p+1][1] = d[3];
            }
        };
        ldfr(0, 0);
#pragma unroll
        for (int ks = 0; ks < 4; ks++) {
            const int cur = ks & 1, nxt = cur ^ 1;
            if (ks < 3) ldfr(ks + 1, nxt);
#pragma unroll
            for (int j = 0; j < 4; j++)
#pragma unroll
                for (int i = 0; i < 4; i++) {
                    mma16(accg[i][j], af[cur][i], b1f[cur][j]);
                    mma16(accu[i][j], af[cur][i], b3f[cur][j]);
                }
        }
    }

    __half* hb = g_hh + ((size_t)e * T_TOK + m0) * H_DIM + n0;
#pragma unroll
    for (int i = 0; i < 4; i++) {
        const int r0 = warp_m + i * 16 + gq;
        const int r1 = r0 + 8;
#pragma unroll
        for (int j = 0; j < 4; j++) {
            const int col = warp_n + j * 8 + tq * 2;
            if (m0 + r0 < cnt) {
                half2 o = __floats2half2_rn(silu_mul(accg[i][j][0], accu[i][j][0]),
                                            silu_mul(accg[i][j][1], accu[i][j][1]));
                *(half2*)(hb + (size_t)r0 * H_DIM + col) = o;
            }
            if (m0 + r1 < cnt) {
                half2 o = __floats2half2_rn(silu_mul(accg[i][j][2], accu[i][j][2]),
                                            silu_mul(accg[i][j][3], accu[i][j][3]));
                *(half2*)(hb + (size_t)r1 * H_DIM + col) = o;
            }
        }
    }
}

// ---------------- gemm2: down = w_m * (H @ w2). BM=128,BN=128,KC=64. warp 64x64.
// 3-stage cp.async pipeline (107 KB SMEM -> 2 CTAs/SM).
__global__ __launch_bounds__(128, 2) void gemm2_mma(){
    const int e = blockIdx.z, cnt = g_cnt[e], m0 = blockIdx.y * 128;
    if (m0 >= cnt) return;
    const int n0 = blockIdx.x * 128;

    const uint32_t sbase = smem_u32(dyn);
    const int tid = threadIdx.x, wid = tid >> 5, lane = tid & 31;
    const int gq = lane >> 2, tq = lane & 3;
    const int warp_m = (wid & 1) * 64, warp_n = (wid >> 1) * 64;

    const __half* hs = g_hh + ((size_t)e * T_TOK + min(m0 + tid, cnt - 1)) * H_DIM;  // + kg
    const int brow = tid >> 1, bhw = (tid & 1) * 64;
    const __half* w2s = g_w2h + ((size_t)e * H_DIM + brow) * D_DIM + n0 + bhw;       // + kg*D
    const uint32_t dA = sbase + (uint32_t)tid * 144u;
    const uint32_t dB = sbase + B2OFFB + (uint32_t)(brow * 272 + bhw * 2);

    auto fill = [&](int c){
        const uint32_t bo = (uint32_t)(c % 3) * BUFB2;
        const int kg = c * KC;
        const __half* pa = hs + kg;
#pragma unroll
        for (int i = 0; i < 8; i++) cpa16(dA + bo + i * 16, pa + i * 8);
        const __half* pb = w2s + (size_t)kg * D_DIM;
#pragma unroll
        for (int i = 0; i < 8; i++) cpa16(dB + bo + i * 16, pb + i * 8);
    };

    uint32_t a_off[4];
#pragma unroll
    for (int i = 0; i < 4; i++)
        a_off[i] = (uint32_t)(((warp_m + i * 16 + (lane & 15)) * 72 + (lane >> 4) * 8) * 2);
    uint32_t b_off[4];
#pragma unroll
    for (int p = 0; p < 4; p++)
        b_off[p] = (uint32_t)(B2OFFB + ((lane & 15) * 136 + warp_n + p * 16 + (lane >> 4) * 8) * 2);

    float acc[4][8][4];
#pragma unroll
    for (int i = 0; i < 4; i++)
#pragma unroll
        for (int j = 0; j < 8; j++)
#pragma unroll
            for (int q = 0; q < 4; q++) acc[i][j][q] = 0.f;

    const int NC = H_DIM / KC;  // 44
    fill(0); CP_COMMIT();
    fill(1); CP_COMMIT();

    for (int c = 0; c < NC; c++) {
        CP_WAIT1();
        __syncthreads();
        if (c + 2 < NC) fill(c + 2);
        CP_COMMIT();

        const uint32_t abuf = sbase + (uint32_t)(c % 3) * BUFB2;
        uint32_t af[2][4][4], bf[2][8][2];

        auto ldfr = [&](int ks, int buf){
#pragma unroll
            for (int i = 0; i < 4; i++) ldsm4(af[buf][i], abuf + a_off[i] + ks * 32);
#pragma unroll
            for (int p = 0; p < 4; p++) {
                uint32_t d[4];
                ldsm4t(d, abuf + b_off[p] + ks * 4352);
                bf[buf][2*p][0] = d[0]; bf[buf][2*p][1] = d[1];
                bf[buf][2*p+1][0] = d[2]; bf[buf][2*p+1][1] = d[3];
            }
        };
        ldfr(0, 0);
#pragma unroll
        for (int ks = 0; ks < 4; ks++) {
            const int cur = ks & 1, nxt = cur ^ 1;
            if (ks < 3) ldfr(ks + 1, nxt);
#pragma unroll
            for (int j = 0; j < 8; j++)
#pragma unroll
                for (int i = 0; i < 4; i++) mma16(acc[i][j], af[cur][i], bf[cur][j]);
        }
    }

    float* db = g_down + ((size_t)e * T_TOK + m0) * D_DIM + n0;
#pragma unroll
    for (int i = 0; i < 4; i++) {
        const int r0 = warp_m + i * 16 + gq;
        const int r1 = r0 + 8;
        const float wg0 = g_slot_w[e * T_TOK + min(m0 + r0, cnt - 1)];
        const float wg1 = g_slot_w[e * T_TOK + min(m0 + r1, cnt - 1)];
#pragma unroll
        for (int j = 0; j < 8; j++) {
            const int col = warp_n + j * 8 + tq * 2;
            if (m0 + r0 < cnt) {
                float2 o; o.x = acc[i][j][0] * wg0; o.y = acc[i][j][1] * wg0;
                *(float2*)(db + (size_t)r0 * D_DIM + col) = o;
            }
            if (m0 + r1 < cnt) {
                float2 o; o.x = acc[i][j][2] * wg1; o.y = acc[i][j][3] * wg1;
                *(float2*)(db + (size_t)r1 * D_DIM + col) = o;
            }
        }
    }
}

// ---------------- launch ----------------
extern "C" void kernel_launch(void* const* d_in, const int* in_sizes, int n_in,
                              void* d_out, int out_size){
    const float* x  = (const float*)d_in[0];
    const float* wg = (const float*)d_in[1];
    const float* w1 = (const float*)d_in[2];
    const float* w2 = (const float*)d_in[3];
    const float* w3 = (const float*)d_in[4];
    float* out = (float*)d_out;

    const int smem13 = 3 * BUFB13;  // 110592
    const int smem2  = 3 * BUFB2;   // 107520
    cudaFuncSetAttribute(gemm13_mma, cudaFuncAttributeMaxDynamicSharedMemorySize, smem13);
    cudaFuncSetAttribute(gemm2_mma,  cudaFuncAttributeMaxDynamicSharedMemorySize, smem2);

    __half* xh;  cudaGetSymbolAddress((void**)&xh,  g_xh);
    __half* w1h; cudaGetSymbolAddress((void**)&w1h, g_w1h);
    __half* w3h; cudaGetSymbolAddress((void**)&w3h, g_w3h);
    __half* w2h; cudaGetSymbolAddress((void**)&w2h, g_w2h);

    const int nw8 = (E_NUM * D_DIM * H_DIM) / 8;
    const int nx8 = (T_TOK * D_DIM) / 8;
    const int ntot = nx8 + 3 * nw8;

    zero_cnt_kernel<<<1, 32>>>();
    gating_kernel<<<T_TOK, 256>>>(x, wg);
    cvt_all_kernel<<<(ntot + 255) / 256, 256>>>(x, w1, w3, w2, xh, w1h, w3h, w2h);
    gemm13_mma<<<dim3(H_DIM / 64, T_TOK / 128, E_NUM), 128, smem13>>>();
    gemm2_mma<<<dim3(D_DIM / 128, T_TOK / 128, E_NUM), 128, smem2>>>();
    combine_kernel<<<T_TOK, 256>>>(out);
}

// round 13
// speedup vs baseline: 1.4010x; 1.0057x over previous
#include <cuda_runtime.h>
#include <cuda_fp16.h>
#include <math.h>
#include <stdint.h>

#define T_TOK 4096
#define D_DIM 1024
#define E_NUM 8
#define H_DIM 2816
#define KC 64

__device__ int   g_cnt[E_NUM];
__device__ int   g_slot_tok[E_NUM * T_TOK];
__device__ float g_slot_w[E_NUM * T_TOK];
__device__ __half g_xh[(size_t)T_TOK * D_DIM];
__device__ __half g_w1h[(size_t)E_NUM * D_DIM * H_DIM];
__device__ __half g_w3h[(size_t)E_NUM * D_DIM * H_DIM];
__device__ __half g_w2h[(size_t)E_NUM * H_DIM * D_DIM];
__device__ __half g_hh[(size_t)E_NUM * T_TOK * H_DIM];

// ---------------- helpers ----------------
__device__ __forceinline__ uint32_t smem_u32(const void* p){
    uint32_t a; asm("{ .reg .u64 t; cvta.to.shared.u64 t, %1; cvt.u32.u64 %0, t; }" : "=r"(a) : "l"(p)); return a;
}
__device__ __forceinline__ void mma16(float* c, const uint32_t* a, const uint32_t* b){
    asm volatile("mma.sync.aligned.m16n8k16.row.col.f32.f16.f16.f32 "
        "{%0,%1,%2,%3}, {%4,%5,%6,%7}, {%8,%9}, {%0,%1,%2,%3};"
        : "+f"(c[0]), "+f"(c[1]), "+f"(c[2]), "+f"(c[3])
        : "r"(a[0]), "r"(a[1]), "r"(a[2]), "r"(a[3]), "r"(b[0]), "r"(b[1]));
}
__device__ __forceinline__ void ldsm4(uint32_t* r, uint32_t addr){
    asm volatile("ldmatrix.sync.aligned.m8n8.x4.shared.b16 {%0,%1,%2,%3}, [%4];"
        : "=r"(r[0]), "=r"(r[1]), "=r"(r[2]), "=r"(r[3]) : "r"(addr));
}
__device__ __forceinline__ void ldsm4t(uint32_t* r, uint32_t addr){
    asm volatile("ldmatrix.sync.aligned.m8n8.x4.trans.shared.b16 {%0,%1,%2,%3}, [%4];"
        : "=r"(r[0]), "=r"(r[1]), "=r"(r[2]), "=r"(r[3]) : "r"(addr));
}
__device__ __forceinline__ float silu_mul(float g, float u){
    return (g / (1.f + expf(-g))) * u;
}
__device__ __forceinline__ void cpa16(uint32_t dst, const void* src){
    asm volatile("cp.async.cg.shared.global [%0], [%1], 16;" :: "r"(dst), "l"(src) : "memory");
}
#define CP_COMMIT() asm volatile("cp.async.commit_group;" ::: "memory")
#define CP_WAIT1()  asm volatile("cp.async.wait_group 1;" ::: "memory")

// ---------------- small kernels ----------------
// zero out[] (poisoned by harness) and the expert counters
__global__ __launch_bounds__(256) void zero_out_kernel(float4* __restrict__ out){
    const int i = blockIdx.x * 256 + threadIdx.x;
    out[i] = make_float4(0.f, 0.f, 0.f, 0.f);
    if (i < E_NUM) g_cnt[i] = 0;
}

// fused fp32 -> fp16 pre-round over x, w1, w3, w2 (8 elements/thread)
__global__ __launch_bounds__(256) void cvt_all_kernel(const float* __restrict__ x,
                                                      const float* __restrict__ w1,
                                                      const float* __restrict__ w3,
                                                      const float* __restrict__ w2,
                                                      __half* __restrict__ xh,
                                                      __half* __restrict__ w1h,
                                                      __half* __restrict__ w3h,
                                                      __half* __restrict__ w2h){
    const int nx8 = (T_TOK * D_DIM) / 8;
    const int nw8 = (E_NUM * D_DIM * H_DIM) / 8;
    const int i = blockIdx.x * 256 + threadIdx.x;
    const float* src; __half* dst; size_t off;
    if (i < nx8) { src = x; dst = xh; off = (size_t)i; }
    else {
        const int j = i - nx8;
        const int arr = j / nw8;
        off = (size_t)(j - arr * nw8);
        if (arr == 0)      { src = w1; dst = w1h; }
        else if (arr == 1) { src = w3; dst = w3h; }
        else if (arr == 2) { src = w2; dst = w2h; }
        else return;
    }
    const float4* s4 = (const float4*)src + 2 * off;
    float4 a = s4[0], b = s4[1];
    half2 h0 = __floats2half2_rn(a.x, a.y);
    half2 h1 = __floats2half2_rn(a.z, a.w);
    half2 h2 = __floats2half2_rn(b.x, b.y);
    half2 h3 = __floats2half2_rn(b.z, b.w);
    uint4 o;
    o.x = *(uint32_t*)&h0; o.y = *(uint32_t*)&h1;
    o.z = *(uint32_t*)&h2; o.w = *(uint32_t*)&h3;
    *(uint4*)(dst + 8 * off) = o;
}

__global__ __launch_bounds__(256) void gating_kernel(const float* __restrict__ x,
                                                     const float* __restrict__ wg){
    __shared__ float s_red[E_NUM][256];
    const int t = blockIdx.x, tid = threadIdx.x;
    const float* xr = x + (size_t)t * D_DIM;
    float part[E_NUM];
#pragma unroll
    for (int e = 0; e < E_NUM; e++) part[e] = 0.f;
    for (int d = tid; d < D_DIM; d += 256) {
        const float xv = xr[d];
        const float* w = wg + (size_t)d * E_NUM;
#pragma unroll
        for (int e = 0; e < E_NUM; e++) part[e] += xv * w[e];
    }
#pragma unroll
    for (int e = 0; e < E_NUM; e++) s_red[e][tid] = part[e];
    __syncthreads();
    for (int s = 128; s > 0; s >>= 1) {
        if (tid < s) {
#pragma unroll
            for (int e = 0; e < E_NUM; e++) s_red[e][tid] += s_red[e][tid + s];
        }
        __syncthreads();
    }
    if (tid == 0) {
        float p[E_NUM]; float mx = -1e30f;
#pragma unroll
        for (int e = 0; e < E_NUM; e++) mx = fmaxf(mx, s_red[e][0]);
#pragma unroll
        for (int e = 0; e < E_NUM; e++) p[e] = expf(s_red[e][0] - mx);
        int i1 = 0;
#pragma unroll
        for (int e = 1; e < E_NUM; e++) if (p[e] > p[i1]) i1 = e;
        int i2 = (i1 == 0) ? 1 : 0;
#pragma unroll
        for (int e = 0; e < E_NUM; e++) if (e != i1 && p[e] > p[i2]) i2 = e;
        const float ws = p[i1] + p[i2];
        const int s0 = atomicAdd(&g_cnt[i1], 1);
        const int s1 = atomicAdd(&g_cnt[i2], 1);
        g_slot_tok[i1 * T_TOK + s0] = t;  g_slot_w[i1 * T_TOK + s0] = p[i1] / ws;
        g_slot_tok[i2 * T_TOK + s1] = t;  g_slot_w[i2 * T_TOK + s1] = p[i2] / ws;
    }
}

// SMEM layouts in halves. A[128][72] rows pitch 144B (bank step 4, conflict-free ldsm).
// gemm13: A(9216) | B1[64][72](4608) | B3[64][72](4608) -> 18432 halves = 36864 B/buf, 3 stages
// gemm2 : A(9216) | B[64][136](8704)                     -> 17920 halves = 35840 B/buf, 3 stages
#define BUFB13 36864
#define B1OFFB 18432
#define B3OFFB 27648
#define BUFB2  35840
#define B2OFFB 18432

extern __shared__ uint32_t dyn[];

// ---------------- gemm13: h = silu(X@w1)*(X@w3). BM=128,BN=64/matrix,KC=64.
// 4 warps (2M x 2N), warp tile 64m x 32n per matrix. 3-stage cp.async pipeline.
__global__ __launch_bounds__(128, 2) void gemm13_mma(){
    const int e = blockIdx.z, cnt = g_cnt[e], m0 = blockIdx.y * 128;
    if (m0 >= cnt) return;
    const int n0 = blockIdx.x * 64;

    __shared__ int s_row[128];
    const uint32_t sbase = smem_u32(dyn);
    const int tid = threadIdx.x, wid = tid >> 5, lane = tid & 31;
    const int gq = lane >> 2, tq = lane & 3;
    const int warp_m = (wid & 1) * 64, warp_n = (wid >> 1) * 32;

    s_row[tid] = g_slot_tok[e * T_TOK + min(m0 + tid, cnt - 1)];
    __syncthreads();

    const __half* xs  = g_xh + (size_t)s_row[tid] * D_DIM;            // + kg
    const int brow = tid >> 1, bhw = (tid & 1) * 32;
    const __half* w1s = g_w1h + ((size_t)e * D_DIM + brow) * H_DIM + n0 + bhw;  // + kg*H
    const __half* w3s = g_w3h + ((size_t)e * D_DIM + brow) * H_DIM + n0 + bhw;
    const uint32_t dA  = sbase + (uint32_t)tid * 144u;
    const uint32_t dB1 = sbase + B1OFFB + (uint32_t)(brow * 144 + bhw * 2);
    const uint32_t dB3 = sbase + B3OFFB + (uint32_t)(brow * 144 + bhw * 2);

    auto fill = [&](int c){
        const uint32_t bo = (uint32_t)(c % 3) * BUFB13;
        const int kg = c * KC;
        const __half* pa = xs + kg;
#pragma unroll
        for (int i = 0; i < 8; i++) cpa16(dA + bo + i * 16, pa + i * 8);
        const __half* p1 = w1s + (size_t)kg * H_DIM;
        const __half* p3 = w3s + (size_t)kg * H_DIM;
#pragma unroll
        for (int i = 0; i < 4; i++) cpa16(dB1 + bo + i * 16, p1 + i * 8);
#pragma unroll
        for (int i = 0; i < 4; i++) cpa16(dB3 + bo + i * 16, p3 + i * 8);
    };

    // ldmatrix lane offsets (bytes)
    uint32_t a_off[4];
#pragma unroll
    for (int i = 0; i < 4; i++)
        a_off[i] = (uint32_t)(((warp_m + i * 16 + (lane & 15)) * 72 + (lane >> 4) * 8) * 2);
    uint32_t b_off[2];
#pragma unroll
    for (int p = 0; p < 2; p++)
        b_off[p] = (uint32_t)(B1OFFB + ((lane & 15) * 72 + warp_n + p * 16 + (lane >> 4) * 8) * 2);

    float accg[4][4][4], accu[4][4][4];
#pragma unroll
    for (int i = 0; i < 4; i++)
#pragma unroll
        for (int j = 0; j < 4; j++)
#pragma unroll
            for (int q = 0; q < 4; q++) { accg[i][j][q] = 0.f; accu[i][j][q] = 0.f; }

    const int NC = D_DIM / KC;  // 16
    fill(0); CP_COMMIT();
    fill(1); CP_COMMIT();

    for (int c = 0; c < NC; c++) {
        CP_WAIT1();
        __syncthreads();
        if (c + 2 < NC) fill(c + 2);
        CP_COMMIT();

        const uint32_t abuf = sbase + (uint32_t)(c % 3) * BUFB13;

        uint32_t af[2][4][4], b1f[2][4][2], b3f[2][4][2];
        auto ldfr = [&](int ks, int buf){
#pragma unroll
            for (int i = 0; i < 4; i++) ldsm4(af[buf][i], abuf + a_off[i] + ks * 32);
#pragma unroll
            for (int p = 0; p < 2; p++) {
                uint32_t d[4];
                ldsm4t(d, abuf + b_off[p] + ks * 2304);
                b1f[buf][2*p][0] = d[0]; b1f[buf][2*p][1] = d[1];
                b1f[buf][2*p+1][0] = d[2]; b1f[buf][2*p+1][1] = d[3];
                ldsm4t(d, abuf + b_off[p] + 9216 + ks * 2304);
                b3f[buf][2*p][0] = d[0]; b3f[buf][2*p][1] = d[1];
                b3f[buf][2*p+1][0] = d[2]; b3f[buf][2*p+1][1] = d[3];
            }
        };
        ldfr(0, 0);
#pragma unroll
        for (int ks = 0; ks < 4; ks++) {
            const int cur = ks & 1, nxt = cur ^ 1;
            if (ks < 3) ldfr(ks + 1, nxt);
#pragma unroll
            for (int j = 0; j < 4; j++)
#pragma unroll
                for (int i = 0; i < 4; i++) {
                    mma16(accg[i][j], af[cur][i], b1f[cur][j]);
                    mma16(accu[i][j], af[cur][i], b3f[cur][j]);
                }
        }
    }

    __half* hb = g_hh + ((size_t)e * T_TOK + m0) * H_DIM + n0;
#pragma unroll
    for (int i = 0; i < 4; i++) {
        const int r0 = warp_m + i * 16 + gq;
        const int r1 = r0 + 8;
#pragma unroll
        for (int j = 0; j < 4; j++) {
            const int col = warp_n + j * 8 + tq * 2;
            if (m0 + r0 < cnt) {
                half2 o = __floats2half2_rn(silu_mul(accg[i][j][0], accu[i][j][0]),
                                            silu_mul(accg[i][j][1], accu[i][j][1]));
                *(half2*)(hb + (size_t)r0 * H_DIM + col) = o;
            }
            if (m0 + r1 < cnt) {
                half2 o = __floats2half2_rn(silu_mul(accg[i][j][2], accu[i][j][2]),
                                            silu_mul(accg[i][j][3], accu[i][j][3]));
                *(half2*)(hb + (size_t)r1 * H_DIM + col) = o;
            }
        }
    }
}

// ---------------- gemm2: out[tok] += w_m * (H @ w2). BM=128,BN=128,KC=64. warp 64x64.
// 3-stage cp.async pipeline. Epilogue: atomicAdd directly into out (2 addends per
// element, fp add commutative -> bitwise deterministic with zero-initialized out).
__global__ __launch_bounds__(128, 2) void gemm2_mma(float* __restrict__ out){
    const int e = blockIdx.z, cnt = g_cnt[e], m0 = blockIdx.y * 128;
    if (m0 >= cnt) return;
    const int n0 = blockIdx.x * 128;

    const uint32_t sbase = smem_u32(dyn);
    const int tid = threadIdx.x, wid = tid >> 5, lane = tid & 31;
    const int gq = lane >> 2, tq = lane & 3;
    const int warp_m = (wid & 1) * 64, warp_n = (wid >> 1) * 64;

    const __half* hs = g_hh + ((size_t)e * T_TOK + min(m0 + tid, cnt - 1)) * H_DIM;  // + kg
    const int brow = tid >> 1, bhw = (tid & 1) * 64;
    const __half* w2s = g_w2h + ((size_t)e * H_DIM + brow) * D_DIM + n0 + bhw;       // + kg*D
    const uint32_t dA = sbase + (uint32_t)tid * 144u;
    const uint32_t dB = sbase + B2OFFB + (uint32_t)(brow * 272 + bhw * 2);

    auto fill = [&](int c){
        const uint32_t bo = (uint32_t)(c % 3) * BUFB2;
        const int kg = c * KC;
        const __half* pa = hs + kg;
#pragma unroll
        for (int i = 0; i < 8; i++) cpa16(dA + bo + i * 16, pa + i * 8);
        const __half* pb = w2s + (size_t)kg * D_DIM;
#pragma unroll
        for (int i = 0; i < 8; i++) cpa16(dB + bo + i * 16, pb + i * 8);
    };

    uint32_t a_off[4];
#pragma unroll
    for (int i = 0; i < 4; i++)
        a_off[i] = (uint32_t)(((warp_m + i * 16 + (lane & 15)) * 72 + (lane >> 4) * 8) * 2);
    uint32_t b_off[4];
#pragma unroll
    for (int p = 0; p < 4; p++)
        b_off[p] = (uint32_t)(B2OFFB + ((lane & 15) * 136 + warp_n + p * 16 + (lane >> 4) * 8) * 2);

    float acc[4][8][4];
#pragma unroll
    for (int i = 0; i < 4; i++)
#pragma unroll
        for (int j = 0; j < 8; j++)
#pragma unroll
            for (int q = 0; q < 4; q++) acc[i][j][q] = 0.f;

    const int NC = H_DIM / KC;  // 44
    fill(0); CP_COMMIT();
    fill(1); CP_COMMIT();

    for (int c = 0; c < NC; c++) {
        CP_WAIT1();
        __syncthreads();
        if (c + 2 < NC) fill(c + 2);
        CP_COMMIT();

        const uint32_t abuf = sbase + (uint32_t)(c % 3) * BUFB2;
        uint32_t af[2][4][4], bf[2][8][2];

        auto ldfr = [&](int ks, int buf){
#pragma unroll
            for (int i = 0; i < 4; i++) ldsm4(af[buf][i], abuf + a_off[i] + ks * 32);
#pragma unroll
            for (int p = 0; p < 4; p++) {
                uint32_t d[4];
                ldsm4t(d, abuf + b_off[p] + ks * 4352);
                bf[buf][2*p][0] = d[0]; bf[buf][2*p][1] = d[1];
                bf[buf][2*p+1][0] = d[2]; bf[buf][2*p+1][1] = d[3];
            }
        };
        ldfr(0, 0);
#pragma unroll
        for (int ks = 0; ks < 4; ks++) {
            const int cur = ks & 1, nxt = cur ^ 1;
            if (ks < 3) ldfr(ks + 1, nxt);
#pragma unroll
            for (int j = 0; j < 8; j++)
#pragma unroll
                for (int i = 0; i < 4; i++) mma16(acc[i][j], af[cur][i], bf[cur][j]);
        }
    }

    // fused combine: out[tok, n] += wgt * acc  (RED, no return)
#pragma unroll
    for (int i = 0; i < 4; i++) {
        const int r0 = warp_m + i * 16 + gq;
        const int r1 = r0 + 8;
        if (m0 + r0 < cnt) {
            const int   tok0 = g_slot_tok[e * T_TOK + m0 + r0];
            const float wg0  = g_slot_w  [e * T_TOK + m0 + r0];
            float* o0 = out + (size_t)tok0 * D_DIM + n0;
#pragma unroll
            for (int j = 0; j < 8; j++) {
                const int col = warp_n + j * 8 + tq * 2;
                atomicAdd(o0 + col,     acc[i][j][0] * wg0);
                atomicAdd(o0 + col + 1, acc[i][j][1] * wg0);
            }
        }
        if (m0 + r1 < cnt) {
            const int   tok1 = g_slot_tok[e * T_TOK + m0 + r1];
            const float wg1  = g_slot_w  [e * T_TOK + m0 + r1];
            float* o1 = out + (size_t)tok1 * D_DIM + n0;
#pragma unroll
            for (int j = 0; j < 8; j++) {
                const int col = warp_n + j * 8 + tq * 2;
                atomicAdd(o1 + col,     acc[i][j][2] * wg1);
                atomicAdd(o1 + col + 1, acc[i][j][3] * wg1);
            }
        }
    }
}

// ---------------- launch ----------------
extern "C" void kernel_launch(void* const* d_in, const int* in_sizes, int n_in,
                              void* d_out, int out_size){
    const float* x  = (const float*)d_in[0];
    const float* wg = (const float*)d_in[1];
    const float* w1 = (const float*)d_in[2];
    const float* w2 = (const float*)d_in[3];
    const float* w3 = (const float*)d_in[4];
    float* out = (float*)d_out;

    const int smem13 = 3 * BUFB13;  // 110592
    const int smem2  = 3 * BUFB2;   // 107520
    cudaFuncSetAttribute(gemm13_mma, cudaFuncAttributeMaxDynamicSharedMemorySize, smem13);
    cudaFuncSetAttribute(gemm2_mma,  cudaFuncAttributeMaxDynamicSharedMemorySize, smem2);

    __half* xh;  cudaGetSymbolAddress((void**)&xh,  g_xh);
    __half* w1h; cudaGetSymbolAddress((void**)&w1h, g_w1h);
    __half* w3h; cudaGetSymbolAddress((void**)&w3h, g_w3h);
    __half* w2h; cudaGetSymbolAddress((void**)&w2h, g_w2h);

    const int nw8 = (E_NUM * D_DIM * H_DIM) / 8;
    const int nx8 = (T_TOK * D_DIM) / 8;
    const int ntot = nx8 + 3 * nw8;
    const int nout4 = (T_TOK * D_DIM) / 4;  // 1048576 float4

    zero_out_kernel<<<nout4 / 256, 256>>>((float4*)out);
    gating_kernel<<<T_TOK, 256>>>(x, wg);
    cvt_all_kernel<<<(ntot + 255) / 256, 256>>>(x, w1, w3, w2, xh, w1h, w3h, w2h);
    gemm13_mma<<<dim3(H_DIM / 64, T_TOK / 128, E_NUM), 128, smem13>>>();
    gemm2_mma<<<dim3(D_DIM / 128, T_TOK / 128, E_NUM), 128, smem2>>>(out);
}

// round 14
// speedup vs baseline: 1.4355x; 1.0247x over previous
#include <cuda_runtime.h>
#include <cuda_fp16.h>
#include <math.h>
#include <stdint.h>

#define T_TOK 4096
#define D_DIM 1024
#define E_NUM 8
#define H_DIM 2816
#define KC 64

__device__ int   g_cnt[E_NUM];
__device__ int   g_slot_tok[E_NUM * T_TOK];
__device__ float g_slot_w[E_NUM * T_TOK];
__device__ __half g_xh[(size_t)T_TOK * D_DIM];
__device__ __half g_w1h[(size_t)E_NUM * D_DIM * H_DIM];
__device__ __half g_w3h[(size_t)E_NUM * D_DIM * H_DIM];
__device__ __half g_w2h[(size_t)E_NUM * H_DIM * D_DIM];
__device__ __half g_hh[(size_t)E_NUM * T_TOK * H_DIM];

// ---------------- helpers ----------------
__device__ __forceinline__ uint32_t smem_u32(const void* p){
    uint32_t a; asm("{ .reg .u64 t; cvta.to.shared.u64 t, %1; cvt.u32.u64 %0, t; }" : "=r"(a) : "l"(p)); return a;
}
__device__ __forceinline__ void mma16(float* c, const uint32_t* a, const uint32_t* b){
    asm volatile("mma.sync.aligned.m16n8k16.row.col.f32.f16.f16.f32 "
        "{%0,%1,%2,%3}, {%4,%5,%6,%7}, {%8,%9}, {%0,%1,%2,%3};"
        : "+f"(c[0]), "+f"(c[1]), "+f"(c[2]), "+f"(c[3])
        : "r"(a[0]), "r"(a[1]), "r"(a[2]), "r"(a[3]), "r"(b[0]), "r"(b[1]));
}
__device__ __forceinline__ void ldsm4(uint32_t* r, uint32_t addr){
    asm volatile("ldmatrix.sync.aligned.m8n8.x4.shared.b16 {%0,%1,%2,%3}, [%4];"
        : "=r"(r[0]), "=r"(r[1]), "=r"(r[2]), "=r"(r[3]) : "r"(addr));
}
__device__ __forceinline__ void ldsm4t(uint32_t* r, uint32_t addr){
    asm volatile("ldmatrix.sync.aligned.m8n8.x4.trans.shared.b16 {%0,%1,%2,%3}, [%4];"
        : "=r"(r[0]), "=r"(r[1]), "=r"(r[2]), "=r"(r[3]) : "r"(addr));
}
__device__ __forceinline__ float silu_mul(float g, float u){
    return (g / (1.f + expf(-g))) * u;
}
__device__ __forceinline__ void cpa16(uint32_t dst, const void* src){
    asm volatile("cp.async.cg.shared.global [%0], [%1], 16;" :: "r"(dst), "l"(src) : "memory");
}
#define CP_COMMIT() asm volatile("cp.async.commit_group;" ::: "memory")
#define CP_WAIT1()  asm volatile("cp.async.wait_group 1;" ::: "memory")

// ---------------- small kernels ----------------
__global__ void zero_cnt_kernel() { if (threadIdx.x < E_NUM) g_cnt[threadIdx.x] = 0; }

// fused fp32 -> fp16 pre-round over x, w1, w3, w2 (8 elements/thread)
__global__ __launch_bounds__(256) void cvt_all_kernel(const float* __restrict__ x,
                                                      const float* __restrict__ w1,
                                                      const float* __restrict__ w3,
                                                      const float* __restrict__ w2,
                                                      __half* __restrict__ xh,
                                                      __half* __restrict__ w1h,
                                                      __half* __restrict__ w3h,
                                                      __half* __restrict__ w2h){
    const int nx8 = (T_TOK * D_DIM) / 8;
    const int nw8 = (E_NUM * D_DIM * H_DIM) / 8;
    const int i = blockIdx.x * 256 + threadIdx.x;
    const float* src; __half* dst; size_t off;
    if (i < nx8) { src = x; dst = xh; off = (size_t)i; }
    else {
        const int j = i - nx8;
        const int arr = j / nw8;
        off = (size_t)(j - arr * nw8);
        if (arr == 0)      { src = w1; dst = w1h; }
        else if (arr == 1) { src = w3; dst = w3h; }
        else if (arr == 2) { src = w2; dst = w2h; }
        else return;
    }
    const float4* s4 = (const float4*)src + 2 * off;
    float4 a = s4[0], b = s4[1];
    half2 h0 = __floats2half2_rn(a.x, a.y);
    half2 h1 = __floats2half2_rn(a.z, a.w);
    half2 h2 = __floats2half2_rn(b.x, b.y);
    half2 h3 = __floats2half2_rn(b.z, b.w);
    uint4 o;
    o.x = *(uint32_t*)&h0; o.y = *(uint32_t*)&h1;
    o.z = *(uint32_t*)&h2; o.w = *(uint32_t*)&h3;
    *(uint4*)(dst + 8 * off) = o;
}

// gating + zero out[t,:] (out is accumulated into by gemm2's fused combine)
__global__ __launch_bounds__(256) void gating_kernel(const float* __restrict__ x,
                                                     const float* __restrict__ wg,
                                                     float4* __restrict__ out){
    __shared__ float s_red[E_NUM][256];
    const int t = blockIdx.x, tid = threadIdx.x;
    const float* xr = x + (size_t)t * D_DIM;

    // zero this token's output row (256 float4 = 1024 floats)
    out[(size_t)t * (D_DIM / 4) + tid] = make_float4(0.f, 0.f, 0.f, 0.f);

    float part[E_NUM];
#pragma unroll
    for (int e = 0; e < E_NUM; e++) part[e] = 0.f;
    for (int d = tid; d < D_DIM; d += 256) {
        const float xv = xr[d];
        const float* w = wg + (size_t)d * E_NUM;
#pragma unroll
        for (int e = 0; e < E_NUM; e++) part[e] += xv * w[e];
    }
#pragma unroll
    for (int e = 0; e < E_NUM; e++) s_red[e][tid] = part[e];
    __syncthreads();
    for (int s = 128; s > 0; s >>= 1) {
        if (tid < s) {
#pragma unroll
            for (int e = 0; e < E_NUM; e++) s_red[e][tid] += s_red[e][tid + s];
        }
        __syncthreads();
    }
    if (tid == 0) {
        float p[E_NUM]; float mx = -1e30f;
#pragma unroll
        for (int e = 0; e < E_NUM; e++) mx = fmaxf(mx, s_red[e][0]);
#pragma unroll
        for (int e = 0; e < E_NUM; e++) p[e] = expf(s_red[e][0] - mx);
        int i1 = 0;
#pragma unroll
        for (int e = 1; e < E_NUM; e++) if (p[e] > p[i1]) i1 = e;
        int i2 = (i1 == 0) ? 1 : 0;
#pragma unroll
        for (int e = 0; e < E_NUM; e++) if (e != i1 && p[e] > p[i2]) i2 = e;
        const float ws = p[i1] + p[i2];
        const int s0 = atomicAdd(&g_cnt[i1], 1);
        const int s1 = atomicAdd(&g_cnt[i2], 1);
        g_slot_tok[i1 * T_TOK + s0] = t;  g_slot_w[i1 * T_TOK + s0] = p[i1] / ws;
        g_slot_tok[i2 * T_TOK + s1] = t;  g_slot_w[i2 * T_TOK + s1] = p[i2] / ws;
    }
}

// SMEM layouts in halves. A[128][72] rows pitch 144B (bank step 4, conflict-free ldsm).
// gemm13: A(9216) | B1[64][72](4608) | B3[64][72](4608) -> 18432 halves = 36864 B/buf, 3 stages
// gemm2 : A(9216) | B[64][136](8704)                     -> 17920 halves = 35840 B/buf, 3 stages
#define BUFB13 36864
#define B1OFFB 18432
#define B3OFFB 27648
#define BUFB2  35840
#define B2OFFB 18432

extern __shared__ uint32_t dyn[];

// ---------------- gemm13: h = silu(X@w1)*(X@w3). BM=128,BN=64/matrix,KC=64.
// 4 warps (2M x 2N), warp tile 64m x 32n per matrix. 3-stage cp.async pipeline.
__global__ __launch_bounds__(128, 2) void gemm13_mma(){
    const int e = blockIdx.z, cnt = g_cnt[e], m0 = blockIdx.y * 128;
    if (m0 >= cnt) return;
    const int n0 = blockIdx.x * 64;

    __shared__ int s_row[128];
    const uint32_t sbase = smem_u32(dyn);
    const int tid = threadIdx.x, wid = tid >> 5, lane = tid & 31;
    const int gq = lane >> 2, tq = lane & 3;
    const int warp_m = (wid & 1) * 64, warp_n = (wid >> 1) * 32;

    s_row[tid] = g_slot_tok[e * T_TOK + min(m0 + tid, cnt - 1)];
    __syncthreads();

    const __half* xs  = g_xh + (size_t)s_row[tid] * D_DIM;            // + kg
    const int brow = tid >> 1, bhw = (tid & 1) * 32;
    const __half* w1s = g_w1h + ((size_t)e * D_DIM + brow) * H_DIM + n0 + bhw;  // + kg*H
    const __half* w3s = g_w3h + ((size_t)e * D_DIM + brow) * H_DIM + n0 + bhw;
    const uint32_t dA  = sbase + (uint32_t)tid * 144u;
    const uint32_t dB1 = sbase + B1OFFB + (uint32_t)(brow * 144 + bhw * 2);
    const uint32_t dB3 = sbase + B3OFFB + (uint32_t)(brow * 144 + bhw * 2);

    auto fill = [&](int c){
        const uint32_t bo = (uint32_t)(c % 3) * BUFB13;
        const int kg = c * KC;
        const __half* pa = xs + kg;
#pragma unroll
        for (int i = 0; i < 8; i++) cpa16(dA + bo + i * 16, pa + i * 8);
        const __half* p1 = w1s + (size_t)kg * H_DIM;
        const __half* p3 = w3s + (size_t)kg * H_DIM;
#pragma unroll
        for (int i = 0; i < 4; i++) cpa16(dB1 + bo + i * 16, p1 + i * 8);
#pragma unroll
        for (int i = 0; i < 4; i++) cpa16(dB3 + bo + i * 16, p3 + i * 8);
    };

    // ldmatrix lane offsets (bytes)
    uint32_t a_off[4];
#pragma unroll
    for (int i = 0; i < 4; i++)
        a_off[i] = (uint32_t)(((warp_m + i * 16 + (lane & 15)) * 72 + (lane >> 4) * 8) * 2);
    uint32_t b_off[2];
#pragma unroll
    for (int p = 0; p < 2; p++)
        b_off[p] = (uint32_t)(B1OFFB + ((lane & 15) * 72 + warp_n + p * 16 + (lane >> 4) * 8) * 2);

    float accg[4][4][4], accu[4][4][4];
#pragma unroll
    for (int i = 0; i < 4; i++)
#pragma unroll
        for (int j = 0; j < 4; j++)
#pragma unroll
            for (int q = 0; q < 4; q++) { accg[i][j][q] = 0.f; accu[i][j][q] = 0.f; }

    const int NC = D_DIM / KC;  // 16
    fill(0); CP_COMMIT();
    fill(1); CP_COMMIT();

    for (int c = 0; c < NC; c++) {
        CP_WAIT1();
        __syncthreads();

        const uint32_t abuf = sbase + (uint32_t)(c % 3) * BUFB13;

        uint32_t af[2][4][4], b1f[2][4][2], b3f[2][4][2];
        auto ldfr = [&](int ks, int buf){
#pragma unroll
            for (int i = 0; i < 4; i++) ldsm4(af[buf][i], abuf + a_off[i] + ks * 32);
#pragma unroll
            for (int p = 0; p < 2; p++) {
                uint32_t d[4];
                ldsm4t(d, abuf + b_off[p] + ks * 2304);
                b1f[buf][2*p][0] = d[0]; b1f[buf][2*p][1] = d[1];
                b1f[buf][2*p+1][0] = d[2]; b1f[buf][2*p+1][1] = d[3];
                ldsm4t(d, abuf + b_off[p] + 9216 + ks * 2304);
                b3f[buf][2*p][0] = d[0]; b3f[buf][2*p][1] = d[1];
                b3f[buf][2*p+1][0] = d[2]; b3f[buf][2*p+1][1] = d[3];
            }
        };
        // start the chunk's first fragment loads immediately after the barrier;
        // only then issue the (latency-tolerant) next-chunk fill.
        ldfr(0, 0);
        if (c + 2 < NC) fill(c + 2);
        CP_COMMIT();
#pragma unroll
        for (int ks = 0; ks < 4; ks++) {
            const int cur = ks & 1, nxt = cur ^ 1;
            if (ks < 3) ldfr(ks + 1, nxt);
#pragma unroll
            for (int j = 0; j < 4; j++)
#pragma unroll
                for (int i = 0; i < 4; i++) {
                    mma16(accg[i][j], af[cur][i], b1f[cur][j]);
                    mma16(accu[i][j], af[cur][i], b3f[cur][j]);
                }
        }
    }

    __half* hb = g_hh + ((size_t)e * T_TOK + m0) * H_DIM + n0;
#pragma unroll
    for (int i = 0; i < 4; i++) {
        const int r0 = warp_m + i * 16 + gq;
        const int r1 = r0 + 8;
#pragma unroll
        for (int j = 0; j < 4; j++) {
            const int col = warp_n + j * 8 + tq * 2;
            if (m0 + r0 < cnt) {
                half2 o = __floats2half2_rn(silu_mul(accg[i][j][0], accu[i][j][0]),
                                            silu_mul(accg[i][j][1], accu[i][j][1]));
                *(half2*)(hb + (size_t)r0 * H_DIM + col) = o;
            }
            if (m0 + r1 < cnt) {
                half2 o = __floats2half2_rn(silu_mul(accg[i][j][2], accu[i][j][2]),
                                            silu_mul(accg[i][j][3], accu[i][j][3]));
                *(half2*)(hb + (size_t)r1 * H_DIM + col) = o;
            }
        }
    }
}

// ---------------- gemm2: out[tok] += w_m * (H @ w2). BM=128,BN=128,KC=64. warp 64x64.
// 3-stage cp.async pipeline. Epilogue: atomicAdd directly into out (2 addends per
// element, fp add commutative -> bitwise deterministic with zero-initialized out).
__global__ __launch_bounds__(128, 2) void gemm2_mma(float* __restrict__ out){
    const int e = blockIdx.z, cnt = g_cnt[e], m0 = blockIdx.y * 128;
    if (m0 >= cnt) return;
    const int n0 = blockIdx.x * 128;

    const uint32_t sbase = smem_u32(dyn);
    const int tid = threadIdx.x, wid = tid >> 5, lane = tid & 31;
    const int gq = lane >> 2, tq = lane & 3;
    const int warp_m = (wid & 1) * 64, warp_n = (wid >> 1) * 64;

    const __half* hs = g_hh + ((size_t)e * T_TOK + min(m0 + tid, cnt - 1)) * H_DIM;  // + kg
    const int brow = tid >> 1, bhw = (tid & 1) * 64;
    const __half* w2s = g_w2h + ((size_t)e * H_DIM + brow) * D_DIM + n0 + bhw;       // + kg*D
    const uint32_t dA = sbase + (uint32_t)tid * 144u;
    const uint32_t dB = sbase + B2OFFB + (uint32_t)(brow * 272 + bhw * 2);

    auto fill = [&](int c){
        const uint32_t bo = (uint32_t)(c % 3) * BUFB2;
        const int kg = c * KC;
        const __half* pa = hs + kg;
#pragma unroll
        for (int i = 0; i < 8; i++) cpa16(dA + bo + i * 16, pa + i * 8);
        const __half* pb = w2s + (size_t)kg * D_DIM;
#pragma unroll
        for (int i = 0; i < 8; i++) cpa16(dB + bo + i * 16, pb + i * 8);
    };

    uint32_t a_off[4];
#pragma unroll
    for (int i = 0; i < 4; i++)
        a_off[i] = (uint32_t)(((warp_m + i * 16 + (lane & 15)) * 72 + (lane >> 4) * 8) * 2);
    uint32_t b_off[4];
#pragma unroll
    for (int p = 0; p < 4; p++)
        b_off[p] = (uint32_t)(B2OFFB + ((lane & 15) * 136 + warp_n + p * 16 + (lane >> 4) * 8) * 2);

    float acc[4][8][4];
#pragma unroll
    for (int i = 0; i < 4; i++)
#pragma unroll
        for (int j = 0; j < 8; j++)
#pragma unroll
            for (int q = 0; q < 4; q++) acc[i][j][q] = 0.f;

    const int NC = H_DIM / KC;  // 44
    fill(0); CP_COMMIT();
    fill(1); CP_COMMIT();

    for (int c = 0; c < NC; c++) {
        CP_WAIT1();
        __syncthreads();

        const uint32_t abuf = sbase + (uint32_t)(c % 3) * BUFB2;
        uint32_t af[2][4][4], bf[2][8][2];

        auto ldfr = [&](int ks, int buf){
#pragma unroll
            for (int i = 0; i < 4; i++) ldsm4(af[buf][i], abuf + a_off[i] + ks * 32);
#pragma unroll
            for (int p = 0; p < 4; p++) {
                uint32_t d[4];
                ldsm4t(d, abuf + b_off[p] + ks * 4352);
                bf[buf][2*p][0] = d[0]; bf[buf][2*p][1] = d[1];
                bf[buf][2*p+1][0] = d[2]; bf[buf][2*p+1][1] = d[3];
            }
        };
        ldfr(0, 0);
        if (c + 2 < NC) fill(c + 2);
        CP_COMMIT();
#pragma unroll
        for (int ks = 0; ks < 4; ks++) {
            const int cur = ks & 1, nxt = cur ^ 1;
            if (ks < 3) ldfr(ks + 1, nxt);
#pragma unroll
            for (int j = 0; j < 8; j++)
#pragma unroll
                for (int i = 0; i < 4; i++) mma16(acc[i][j], af[cur][i], bf[cur][j]);
        }
    }

    // fused combine: out[tok, n] += wgt * acc  (RED, no return)
#pragma unroll
    for (int i = 0; i < 4; i++) {
        const int r0 = warp_m + i * 16 + gq;
        const int r1 = r0 + 8;
        if (m0 + r0 < cnt) {
            const int   tok0 = g_slot_tok[e * T_TOK + m0 + r0];
            const float wg0  = g_slot_w  [e * T_TOK + m0 + r0];
            float* o0 = out + (size_t)tok0 * D_DIM + n0;
#pragma unroll
            for (int j = 0; j < 8; j++) {
                const int col = warp_n + j * 8 + tq * 2;
                atomicAdd(o0 + col,     acc[i][j][0] * wg0);
                atomicAdd(o0 + col + 1, acc[i][j][1] * wg0);
            }
        }
        if (m0 + r1 < cnt) {
            const int   tok1 = g_slot_tok[e * T_TOK + m0 + r1];
            const float wg1  = g_slot_w  [e * T_TOK + m0 + r1];
            float* o1 = out + (size_t)tok1 * D_DIM + n0;
#pragma unroll
            for (int j = 0; j < 8; j++) {
                const int col = warp_n + j * 8 + tq * 2;
                atomicAdd(o1 + col,     acc[i][j][2] * wg1);
                atomicAdd(o1 + col + 1, acc[i][j][3] * wg1);
            }
        }
    }
}

// ---------------- launch ----------------
extern "C" void kernel_launch(void* const* d_in, const int* in_sizes, int n_in,
                              void* d_out, int out_size){
    const float* x  = (const float*)d_in[0];
    const float* wg = (const float*)d_in[1];
    const float* w1 = (const float*)d_in[2];
    const float* w2 = (const float*)d_in[3];
    const float* w3 = (const float*)d_in[4];
    float* out = (float*)d_out;

    const int smem13 = 3 * BUFB13;  // 110592
    const int smem2  = 3 * BUFB2;   // 107520
    cudaFuncSetAttribute(gemm13_mma, cudaFuncAttributeMaxDynamicSharedMemorySize, smem13);
    cudaFuncSetAttribute(gemm2_mma,  cudaFuncAttributeMaxDynamicSharedMemorySize, smem2);

    __half* xh;  cudaGetSymbolAddress((void**)&xh,  g_xh);
    __half* w1h; cudaGetSymbolAddress((void**)&w1h, g_w1h);
    __half* w3h; cudaGetSymbolAddress((void**)&w3h, g_w3h);
    __half* w2h; cudaGetSymbolAddress((void**)&w2h, g_w2h);

    const int nw8 = (E_NUM * D_DIM * H_DIM) / 8;
    const int nx8 = (T_TOK * D_DIM) / 8;
    const int ntot = nx8 + 3 * nw8;

    zero_cnt_kernel<<<1, 32>>>();
    gating_kernel<<<T_TOK, 256>>>(x, wg, (float4*)out);
    cvt_all_kernel<<<(ntot + 255) / 256, 256>>>(x, w1, w3, w2, xh, w1h, w3h, w2h);
    gemm13_mma<<<dim3(H_DIM / 64, T_TOK / 128, E_NUM), 128, smem13>>>();
    gemm2_mma<<<dim3(D_DIM / 128, T_TOK / 128, E_NUM), 128, smem2>>>(out);
}

// round 15
// speedup vs baseline: 1.4518x; 1.0114x over previous
#include <cuda_runtime.h>
#include <cuda_fp16.h>
#include <math.h>
#include <stdint.h>

#define T_TOK 4096
#define D_DIM 1024
#define E_NUM 8
#define H_DIM 2816
#define KC 64

__device__ int   g_cnt[E_NUM];
__device__ int   g_slot_tok[E_NUM * T_TOK];
__device__ float g_slot_w[E_NUM * T_TOK];
__device__ __half g_xh[(size_t)T_TOK * D_DIM];
__device__ __half g_w1h[(size_t)E_NUM * D_DIM * H_DIM];
__device__ __half g_w3h[(size_t)E_NUM * D_DIM * H_DIM];
__device__ __half g_w2h[(size_t)E_NUM * H_DIM * D_DIM];
__device__ __half g_hh[(size_t)E_NUM * T_TOK * H_DIM];

// ---------------- helpers ----------------
__device__ __forceinline__ uint32_t smem_u32(const void* p){
    uint32_t a; asm("{ .reg .u64 t; cvta.to.shared.u64 t, %1; cvt.u32.u64 %0, t; }" : "=r"(a) : "l"(p)); return a;
}
__device__ __forceinline__ void mma16(float* c, const uint32_t* a, const uint32_t* b){
    asm volatile("mma.sync.aligned.m16n8k16.row.col.f32.f16.f16.f32 "
        "{%0,%1,%2,%3}, {%4,%5,%6,%7}, {%8,%9}, {%0,%1,%2,%3};"
        : "+f"(c[0]), "+f"(c[1]), "+f"(c[2]), "+f"(c[3])
        : "r"(a[0]), "r"(a[1]), "r"(a[2]), "r"(a[3]), "r"(b[0]), "r"(b[1]));
}
__device__ __forceinline__ void ldsm4(uint32_t* r, uint32_t addr){
    asm volatile("ldmatrix.sync.aligned.m8n8.x4.shared.b16 {%0,%1,%2,%3}, [%4];"
        : "=r"(r[0]), "=r"(r[1]), "=r"(r[2]), "=r"(r[3]) : "r"(addr));
}
__device__ __forceinline__ void ldsm4t(uint32_t* r, uint32_t addr){
    asm volatile("ldmatrix.sync.aligned.m8n8.x4.trans.shared.b16 {%0,%1,%2,%3}, [%4];"
        : "=r"(r[0]), "=r"(r[1]), "=r"(r[2]), "=r"(r[3]) : "r"(addr));
}
__device__ __forceinline__ float silu_mul(float g, float u){
    return (g / (1.f + expf(-g))) * u;
}
__device__ __forceinline__ void cpa16(uint32_t dst, const void* src){
    asm volatile("cp.async.cg.shared.global [%0], [%1], 16;" :: "r"(dst), "l"(src) : "memory");
}
#define CP_COMMIT() asm volatile("cp.async.commit_group;" ::: "memory")
#define CP_WAIT1()  asm volatile("cp.async.wait_group 1;" ::: "memory")

// ---------------- small kernels ----------------
__global__ void zero_cnt_kernel() { if (threadIdx.x < E_NUM) g_cnt[threadIdx.x] = 0; }

// fused prep: blocks [0, T_TOK) do gating (+ zero out row); the rest convert
// x/w1/w3/w2 to fp16 (8 elements per thread). The two sections are independent.
__global__ __launch_bounds__(256) void prep_kernel(const float* __restrict__ x,
                                                   const float* __restrict__ wg,
                                                   float4* __restrict__ out,
                                                   const float* __restrict__ w1,
                                                   const float* __restrict__ w3,
                                                   const float* __restrict__ w2,
                                                   __half* __restrict__ xh,
                                                   __half* __restrict__ w1h,
                                                   __half* __restrict__ w3h,
                                                   __half* __restrict__ w2h){
    const int tid = threadIdx.x;
    if (blockIdx.x < T_TOK) {
        // ---- gating section ----
        __shared__ float s_red[E_NUM][256];
        const int t = blockIdx.x;
        const float* xr = x + (size_t)t * D_DIM;

        out[(size_t)t * (D_DIM / 4) + tid] = make_float4(0.f, 0.f, 0.f, 0.f);

        float part[E_NUM];
#pragma unroll
        for (int e = 0; e < E_NUM; e++) part[e] = 0.f;
        for (int d = tid; d < D_DIM; d += 256) {
            const float xv = xr[d];
            const float* w = wg + (size_t)d * E_NUM;
#pragma unroll
            for (int e = 0; e < E_NUM; e++) part[e] += xv * w[e];
        }
#pragma unroll
        for (int e = 0; e < E_NUM; e++) s_red[e][tid] = part[e];
        __syncthreads();
        for (int s = 128; s > 0; s >>= 1) {
            if (tid < s) {
#pragma unroll
                for (int e = 0; e < E_NUM; e++) s_red[e][tid] += s_red[e][tid + s];
            }
            __syncthreads();
        }
        if (tid == 0) {
            float p[E_NUM]; float mx = -1e30f;
#pragma unroll
            for (int e = 0; e < E_NUM; e++) mx = fmaxf(mx, s_red[e][0]);
#pragma unroll
            for (int e = 0; e < E_NUM; e++) p[e] = expf(s_red[e][0] - mx);
            int i1 = 0;
#pragma unroll
            for (int e = 1; e < E_NUM; e++) if (p[e] > p[i1]) i1 = e;
            int i2 = (i1 == 0) ? 1 : 0;
#pragma unroll
            for (int e = 0; e < E_NUM; e++) if (e != i1 && p[e] > p[i2]) i2 = e;
            const float ws = p[i1] + p[i2];
            const int s0 = atomicAdd(&g_cnt[i1], 1);
            const int s1 = atomicAdd(&g_cnt[i2], 1);
            g_slot_tok[i1 * T_TOK + s0] = t;  g_slot_w[i1 * T_TOK + s0] = p[i1] / ws;
            g_slot_tok[i2 * T_TOK + s1] = t;  g_slot_w[i2 * T_TOK + s1] = p[i2] / ws;
        }
    } else {
        // ---- cvt section ----
        const int nx8 = (T_TOK * D_DIM) / 8;
        const int nw8 = (E_NUM * D_DIM * H_DIM) / 8;
        const int i = (blockIdx.x - T_TOK) * 256 + tid;
        const float* src; __half* dst; size_t off;
        if (i < nx8) { src = x; dst = xh; off = (size_t)i; }
        else {
            const int j = i - nx8;
            const int arr = j / nw8;
            off = (size_t)(j - arr * nw8);
            if (arr == 0)      { src = w1; dst = w1h; }
            else if (arr == 1) { src = w3; dst = w3h; }
            else if (arr == 2) { src = w2; dst = w2h; }
            else return;
        }
        const float4* s4 = (const float4*)src + 2 * off;
        float4 a = s4[0], b = s4[1];
        half2 h0 = __floats2half2_rn(a.x, a.y);
        half2 h1 = __floats2half2_rn(a.z, a.w);
        half2 h2 = __floats2half2_rn(b.x, b.y);
        half2 h3 = __floats2half2_rn(b.z, b.w);
        uint4 o;
        o.x = *(uint32_t*)&h0; o.y = *(uint32_t*)&h1;
        o.z = *(uint32_t*)&h2; o.w = *(uint32_t*)&h3;
        *(uint4*)(dst + 8 * off) = o;
    }
}

// SMEM layouts in halves. A[128][72] rows pitch 144B (bank step 4, conflict-free ldsm).
// gemm13: A(9216) | B1[64][72](4608) | B3[64][72](4608) -> 18432 halves = 36864 B/buf, 3 stages
// gemm2 : A(9216) | B[64][136](8704)                     -> 17920 halves = 35840 B/buf, 3 stages
#define BUFB13 36864
#define B1OFFB 18432
#define B3OFFB 27648
#define BUFB2  35840
#define B2OFFB 18432

extern __shared__ uint32_t dyn[];

// ---------------- gemm13: h = silu(X@w1)*(X@w3). BM=128,BN=64/matrix,KC=64.
// 4 warps (2M x 2N), warp tile 64m x 32n per matrix. 3-stage cp.async pipeline.
__global__ __launch_bounds__(128, 2) void gemm13_mma(){
    const int e = blockIdx.z, cnt = g_cnt[e], m0 = blockIdx.y * 128;
    if (m0 >= cnt) return;
    const int n0 = blockIdx.x * 64;

    __shared__ int s_row[128];
    const uint32_t sbase = smem_u32(dyn);
    const int tid = threadIdx.x, wid = tid >> 5, lane = tid & 31;
    const int gq = lane >> 2, tq = lane & 3;
    const int warp_m = (wid & 1) * 64, warp_n = (wid >> 1) * 32;

    s_row[tid] = g_slot_tok[e * T_TOK + min(m0 + tid, cnt - 1)];
    __syncthreads();

    const __half* xs  = g_xh + (size_t)s_row[tid] * D_DIM;            // + kg
    const int brow = tid >> 1, bhw = (tid & 1) * 32;
    const __half* w1s = g_w1h + ((size_t)e * D_DIM + brow) * H_DIM + n0 + bhw;  // + kg*H
    const __half* w3s = g_w3h + ((size_t)e * D_DIM + brow) * H_DIM + n0 + bhw;
    const uint32_t dA  = sbase + (uint32_t)tid * 144u;
    const uint32_t dB1 = sbase + B1OFFB + (uint32_t)(brow * 144 + bhw * 2);
    const uint32_t dB3 = sbase + B3OFFB + (uint32_t)(brow * 144 + bhw * 2);

    auto fill = [&](int c){
        const uint32_t bo = (uint32_t)(c % 3) * BUFB13;
        const int kg = c * KC;
        const __half* pa = xs + kg;
#pragma unroll
        for (int i = 0; i < 8; i++) cpa16(dA + bo + i * 16, pa + i * 8);
        const __half* p1 = w1s + (size_t)kg * H_DIM;
        const __half* p3 = w3s + (size_t)kg * H_DIM;
#pragma unroll
        for (int i = 0; i < 4; i++) cpa16(dB1 + bo + i * 16, p1 + i * 8);
#pragma unroll
        for (int i = 0; i < 4; i++) cpa16(dB3 + bo + i * 16, p3 + i * 8);
    };

    // ldmatrix lane offsets (bytes)
    uint32_t a_off[4];
#pragma unroll
    for (int i = 0; i < 4; i++)
        a_off[i] = (uint32_t)(((warp_m + i * 16 + (lane & 15)) * 72 + (lane >> 4) * 8) * 2);
    uint32_t b_off[2];
#pragma unroll
    for (int p = 0; p < 2; p++)
        b_off[p] = (uint32_t)(B1OFFB + ((lane & 15) * 72 + warp_n + p * 16 + (lane >> 4) * 8) * 2);

    float accg[4][4][4], accu[4][4][4];
#pragma unroll
    for (int i = 0; i < 4; i++)
#pragma unroll
        for (int j = 0; j < 4; j++)
#pragma unroll
            for (int q = 0; q < 4; q++) { accg[i][j][q] = 0.f; accu[i][j][q] = 0.f; }

    const int NC = D_DIM / KC;  // 16
    fill(0); CP_COMMIT();
    fill(1); CP_COMMIT();

    for (int c = 0; c < NC; c++) {
        CP_WAIT1();
        __syncthreads();

        const uint32_t abuf = sbase + (uint32_t)(c % 3) * BUFB13;

        uint32_t af[2][4][4], b1f[2][4][2], b3f[2][4][2];
        auto ldfr = [&](int ks, int buf){
#pragma unroll
            for (int i = 0; i < 4; i++) ldsm4(af[buf][i], abuf + a_off[i] + ks * 32);
#pragma unroll
            for (int p = 0; p < 2; p++) {
                uint32_t d[4];
                ldsm4t(d, abuf + b_off[p] + ks * 2304);
                b1f[buf][2*p][0] = d[0]; b1f[buf][2*p][1] = d[1];
                b1f[buf][2*p+1][0] = d[2]; b1f[buf][2*p+1][1] = d[3];
                ldsm4t(d, abuf + b_off[p] + 9216 + ks * 2304);
                b3f[buf][2*p][0] = d[0]; b3f[buf][2*p][1] = d[1];
                b3f[buf][2*p+1][0] = d[2]; b3f[buf][2*p+1][1] = d[3];
            }
        };
        // start the chunk's first fragment loads immediately after the barrier;
        // only then issue the (latency-tolerant) next-chunk fill.
        ldfr(0, 0);
        if (c + 2 < NC) fill(c + 2);
        CP_COMMIT();
#pragma unroll
        for (int ks = 0; ks < 4; ks++) {
            const int cur = ks & 1, nxt = cur ^ 1;
            if (ks < 3) ldfr(ks + 1, nxt);
#pragma unroll
            for (int j = 0; j < 4; j++)
#pragma unroll
                for (int i = 0; i < 4; i++) {
                    mma16(accg[i][j], af[cur][i], b1f[cur][j]);
                    mma16(accu[i][j], af[cur][i], b3f[cur][j]);
                }
        }
    }

    __half* hb = g_hh + ((size_t)e * T_TOK + m0) * H_DIM + n0;
#pragma unroll
    for (int i = 0; i < 4; i++) {
        const int r0 = warp_m + i * 16 + gq;
        const int r1 = r0 + 8;
#pragma unroll
        for (int j = 0; j < 4; j++) {
            const int col = warp_n + j * 8 + tq * 2;
            if (m0 + r0 < cnt) {
                half2 o = __floats2half2_rn(silu_mul(accg[i][j][0], accu[i][j][0]),
                                            silu_mul(accg[i][j][1], accu[i][j][1]));
                *(half2*)(hb + (size_t)r0 * H_DIM + col) = o;
            }
            if (m0 + r1 < cnt) {
                half2 o = __floats2half2_rn(silu_mul(accg[i][j][2], accu[i][j][2]),
                                            silu_mul(accg[i][j][3], accu[i][j][3]));
                *(half2*)(hb + (size_t)r1 * H_DIM + col) = o;
            }
        }
    }
}

// ---------------- gemm2: out[tok] += w_m * (H @ w2). BM=128,BN=128,KC=64. warp 64x64.
// 3-stage cp.async pipeline. Epilogue: atomicAdd directly into out (2 addends per
// element, fp add commutative -> bitwise deterministic with zero-initialized out).
__global__ __launch_bounds__(128, 2) void gemm2_mma(float* __restrict__ out){
    const int e = blockIdx.z, cnt = g_cnt[e], m0 = blockIdx.y * 128;
    if (m0 >= cnt) return;
    const int n0 = blockIdx.x * 128;

    const uint32_t sbase = smem_u32(dyn);
    const int tid = threadIdx.x, wid = tid >> 5, lane = tid & 31;
    const int gq = lane >> 2, tq = lane & 3;
    const int warp_m = (wid & 1) * 64, warp_n = (wid >> 1) * 64;

    const __half* hs = g_hh + ((size_t)e * T_TOK + min(m0 + tid, cnt - 1)) * H_DIM;  // + kg
    const int brow = tid >> 1, bhw = (tid & 1) * 64;
    const __half* w2s = g_w2h + ((size_t)e * H_DIM + brow) * D_DIM + n0 + bhw;       // + kg*D
    const uint32_t dA = sbase + (uint32_t)tid * 144u;
    const uint32_t dB = sbase + B2OFFB + (uint32_t)(brow * 272 + bhw * 2);

    auto fill = [&](int c){
        const uint32_t bo = (uint32_t)(c % 3) * BUFB2;
        const int kg = c * KC;
        const __half* pa = hs + kg;
#pragma unroll
        for (int i = 0; i < 8; i++) cpa16(dA + bo + i * 16, pa + i * 8);
        const __half* pb = w2s + (size_t)kg * D_DIM;
#pragma unroll
        for (int i = 0; i < 8; i++) cpa16(dB + bo + i * 16, pb + i * 8);
    };

    uint32_t a_off[4];
#pragma unroll
    for (int i = 0; i < 4; i++)
        a_off[i] = (uint32_t)(((warp_m + i * 16 + (lane & 15)) * 72 + (lane >> 4) * 8) * 2);
    uint32_t b_off[4];
#pragma unroll
    for (int p = 0; p < 4; p++)
        b_off[p] = (uint32_t)(B2OFFB + ((lane & 15) * 136 + warp_n + p * 16 + (lane >> 4) * 8) * 2);

    float acc[4][8][4];
#pragma unroll
    for (int i = 0; i < 4; i++)
#pragma unroll
        for (int j = 0; j < 8; j++)
#pragma unroll
            for (int q = 0; q < 4; q++) acc[i][j][q] = 0.f;

    const int NC = H_DIM / KC;  // 44
    fill(0); CP_COMMIT();
    fill(1); CP_COMMIT();

    for (int c = 0; c < NC; c++) {
        CP_WAIT1();
        __syncthreads();

        const uint32_t abuf = sbase + (uint32_t)(c % 3) * BUFB2;
        uint32_t af[2][4][4], bf[2][8][2];

        auto ldfr = [&](int ks, int buf){
#pragma unroll
            for (int i = 0; i < 4; i++) ldsm4(af[buf][i], abuf + a_off[i] + ks * 32);
#pragma unroll
            for (int p = 0; p < 4; p++) {
                uint32_t d[4];
                ldsm4t(d, abuf + b_off[p] + ks * 4352);
                bf[buf][2*p][0] = d[0]; bf[buf][2*p][1] = d[1];
                bf[buf][2*p+1][0] = d[2]; bf[buf][2*p+1][1] = d[3];
            }
        };
        ldfr(0, 0);
        if (c + 2 < NC) fill(c + 2);
        CP_COMMIT();
#pragma unroll
        for (int ks = 0; ks < 4; ks++) {
            const int cur = ks & 1, nxt = cur ^ 1;
            if (ks < 3) ldfr(ks + 1, nxt);
#pragma unroll
            for (int j = 0; j < 8; j++)
#pragma unroll
                for (int i = 0; i < 4; i++) mma16(acc[i][j], af[cur][i], bf[cur][j]);
        }
    }

    // fused combine: out[tok, n] += wgt * acc  (RED, no return)
#pragma unroll
    for (int i = 0; i < 4; i++) {
        const int r0 = warp_m + i * 16 + gq;
        const int r1 = r0 + 8;
        if (m0 + r0 < cnt) {
            const int   tok0 = g_slot_tok[e * T_TOK + m0 + r0];
            const float wg0  = g_slot_w  [e * T_TOK + m0 + r0];
            float* o0 = out + (size_t)tok0 * D_DIM + n0;
#pragma unroll
            for (int j = 0; j < 8; j++) {
                const int col = warp_n + j * 8 + tq * 2;
                atomicAdd(o0 + col,     acc[i][j][0] * wg0);
                atomicAdd(o0 + col + 1, acc[i][j][1] * wg0);
            }
        }
        if (m0 + r1 < cnt) {
            const int   tok1 = g_slot_tok[e * T_TOK + m0 + r1];
            const float wg1  = g_slot_w  [e * T_TOK + m0 + r1];
            float* o1 = out + (size_t)tok1 * D_DIM + n0;
#pragma unroll
            for (int j = 0; j < 8; j++) {
                const int col = warp_n + j * 8 + tq * 2;
                atomicAdd(o1 + col,     acc[i][j][2] * wg1);
                atomicAdd(o1 + col + 1, acc[i][j][3] * wg1);
            }
        }
    }
}

// ---------------- launch ----------------
extern "C" void kernel_launch(void* const* d_in, const int* in_sizes, int n_in,
                              void* d_out, int out_size){
    const float* x  = (const float*)d_in[0];
    const float* wg = (const float*)d_in[1];
    const float* w1 = (const float*)d_in[2];
    const float* w2 = (const float*)d_in[3];
    const float* w3 = (const float*)d_in[4];
    float* out = (float*)d_out;

    const int smem13 = 3 * BUFB13;  // 110592
    const int smem2  = 3 * BUFB2;   // 107520
    cudaFuncSetAttribute(gemm13_mma, cudaFuncAttributeMaxDynamicSharedMemorySize, smem13);
    cudaFuncSetAttribute(gemm2_mma,  cudaFuncAttributeMaxDynamicSharedMemorySize, smem2);

    __half* xh;  cudaGetSymbolAddress((void**)&xh,  g_xh);
    __half* w1h; cudaGetSymbolAddress((void**)&w1h, g_w1h);
    __half* w3h; cudaGetSymbolAddress((void**)&w3h, g_w3h);
    __half* w2h; cudaGetSymbolAddress((void**)&w2h, g_w2h);

    const int nw8 = (E_NUM * D_DIM * H_DIM) / 8;
    const int nx8 = (T_TOK * D_DIM) / 8;
    const int ntot = nx8 + 3 * nw8;
    const int nprep = T_TOK + (ntot + 255) / 256;

    zero_cnt_kernel<<<1, 32>>>();
    prep_kernel<<<nprep, 256>>>(x, wg, (float4*)out, w1, w3, w2, xh, w1h, w3h, w2h);
    gemm13_mma<<<dim3(H_DIM / 64, T_TOK / 128, E_NUM), 128, smem13>>>();
    gemm2_mma<<<dim3(D_DIM / 128, T_TOK / 128, E_NUM), 128, smem2>>>(out);
}

// round 16
// speedup vs baseline: 1.6196x; 1.1155x over previous
#include <cuda_runtime.h>
#include <cuda_fp16.h>
#include <math.h>
#include <stdint.h>

#define T_TOK 4096
#define D_DIM 1024
#define E_NUM 8
#define H_DIM 2816
#define KC 64

__device__ int   g_cnt[E_NUM];
__device__ int   g_slot_tok[E_NUM * T_TOK];
__device__ float g_slot_w[E_NUM * T_TOK];
__device__ __half g_xh[(size_t)T_TOK * D_DIM];
__device__ __half g_w1h[(size_t)E_NUM * D_DIM * H_DIM];
__device__ __half g_w3h[(size_t)E_NUM * D_DIM * H_DIM];
__device__ __half g_w2h[(size_t)E_NUM * H_DIM * D_DIM];
__device__ __half g_hh[(size_t)E_NUM * T_TOK * H_DIM];

// ---------------- helpers ----------------
__device__ __forceinline__ uint32_t smem_u32(const void* p){
    uint32_t a; asm("{ .reg .u64 t; cvta.to.shared.u64 t, %1; cvt.u32.u64 %0, t; }" : "=r"(a) : "l"(p)); return a;
}
__device__ __forceinline__ void mma16(float* c, const uint32_t* a, const uint32_t* b){
    asm volatile("mma.sync.aligned.m16n8k16.row.col.f32.f16.f16.f32 "
        "{%0,%1,%2,%3}, {%4,%5,%6,%7}, {%8,%9}, {%0,%1,%2,%3};"
        : "+f"(c[0]), "+f"(c[1]), "+f"(c[2]), "+f"(c[3])
        : "r"(a[0]), "r"(a[1]), "r"(a[2]), "r"(a[3]), "r"(b[0]), "r"(b[1]));
}
__device__ __forceinline__ void ldsm4(uint32_t* r, uint32_t addr){
    asm volatile("ldmatrix.sync.aligned.m8n8.x4.shared.b16 {%0,%1,%2,%3}, [%4];"
        : "=r"(r[0]), "=r"(r[1]), "=r"(r[2]), "=r"(r[3]) : "r"(addr));
}
__device__ __forceinline__ void ldsm4t(uint32_t* r, uint32_t addr){
    asm volatile("ldmatrix.sync.aligned.m8n8.x4.trans.shared.b16 {%0,%1,%2,%3}, [%4];"
        : "=r"(r[0]), "=r"(r[1]), "=r"(r[2]), "=r"(r[3]) : "r"(addr));
}
__device__ __forceinline__ float silu_mul(float g, float u){
    return (g / (1.f + expf(-g))) * u;
}
__device__ __forceinline__ void cpa16(uint32_t dst, const void* src){
    asm volatile("cp.async.cg.shared.global [%0], [%1], 16;" :: "r"(dst), "l"(src) : "memory");
}
#define CP_COMMIT() asm volatile("cp.async.commit_group;" ::: "memory")
#define CP_WAIT1()  asm volatile("cp.async.wait_group 1;" ::: "memory")

// ---------------- small kernels ----------------
__global__ void zero_cnt_kernel() { if (threadIdx.x < E_NUM) g_cnt[threadIdx.x] = 0; }

// fused prep: blocks [0, T_TOK) do gating (+ zero out row); the rest convert
// x/w1/w3/w2 to fp16 (8 elements per thread). The two sections are independent.
__global__ __launch_bounds__(256) void prep_kernel(const float* __restrict__ x,
                                                   const float* __restrict__ wg,
                                                   float4* __restrict__ out,
                                                   const float* __restrict__ w1,
                                                   const float* __restrict__ w3,
                                                   const float* __restrict__ w2,
                                                   __half* __restrict__ xh,
                                                   __half* __restrict__ w1h,
                                                   __half* __restrict__ w3h,
                                                   __half* __restrict__ w2h){
    const int tid = threadIdx.x;
    if (blockIdx.x < T_TOK) {
        __shared__ float s_red[E_NUM][256];
        const int t = blockIdx.x;
        const float* xr = x + (size_t)t * D_DIM;

        out[(size_t)t * (D_DIM / 4) + tid] = make_float4(0.f, 0.f, 0.f, 0.f);

        float part[E_NUM];
#pragma unroll
        for (int e = 0; e < E_NUM; e++) part[e] = 0.f;
        for (int d = tid; d < D_DIM; d += 256) {
            const float xv = xr[d];
            const float* w = wg + (size_t)d * E_NUM;
#pragma unroll
            for (int e = 0; e < E_NUM; e++) part[e] += xv * w[e];
        }
#pragma unroll
        for (int e = 0; e < E_NUM; e++) s_red[e][tid] = part[e];
        __syncthreads();
        for (int s = 128; s > 0; s >>= 1) {
            if (tid < s) {
#pragma unroll
                for (int e = 0; e < E_NUM; e++) s_red[e][tid] += s_red[e][tid + s];
            }
            __syncthreads();
        }
        if (tid == 0) {
            float p[E_NUM]; float mx = -1e30f;
#pragma unroll
            for (int e = 0; e < E_NUM; e++) mx = fmaxf(mx, s_red[e][0]);
#pragma unroll
            for (int e = 0; e < E_NUM; e++) p[e] = expf(s_red[e][0] - mx);
            int i1 = 0;
#pragma unroll
            for (int e = 1; e < E_NUM; e++) if (p[e] > p[i1]) i1 = e;
            int i2 = (i1 == 0) ? 1 : 0;
#pragma unroll
            for (int e = 0; e < E_NUM; e++) if (e != i1 && p[e] > p[i2]) i2 = e;
            const float ws = p[i1] + p[i2];
            const int s0 = atomicAdd(&g_cnt[i1], 1);
            const int s1 = atomicAdd(&g_cnt[i2], 1);
            g_slot_tok[i1 * T_TOK + s0] = t;  g_slot_w[i1 * T_TOK + s0] = p[i1] / ws;
            g_slot_tok[i2 * T_TOK + s1] = t;  g_slot_w[i2 * T_TOK + s1] = p[i2] / ws;
        }
    } else {
        const int nx8 = (T_TOK * D_DIM) / 8;
        const int nw8 = (E_NUM * D_DIM * H_DIM) / 8;
        const int i = (blockIdx.x - T_TOK) * 256 + tid;
        const float* src; __half* dst; size_t off;
        if (i < nx8) { src = x; dst = xh; off = (size_t)i; }
        else {
            const int j = i - nx8;
            const int arr = j / nw8;
            off = (size_t)(j - arr * nw8);
            if (arr == 0)      { src = w1; dst = w1h; }
            else if (arr == 1) { src = w3; dst = w3h; }
            else if (arr == 2) { src = w2; dst = w2h; }
            else return;
        }
        const float4* s4 = (const float4*)src + 2 * off;
        float4 a = s4[0], b = s4[1];
        half2 h0 = __floats2half2_rn(a.x, a.y);
        half2 h1 = __floats2half2_rn(a.z, a.w);
        half2 h2 = __floats2half2_rn(b.x, b.y);
        half2 h3 = __floats2half2_rn(b.z, b.w);
        uint4 o;
        o.x = *(uint32_t*)&h0; o.y = *(uint32_t*)&h1;
        o.z = *(uint32_t*)&h2; o.w = *(uint32_t*)&h3;
        *(uint4*)(dst + 8 * off) = o;
    }
}

// SMEM layouts in halves. A[128][72] rows pitch 144B (bank step 4, conflict-free ldsm).
// gemm13: A(9216) | B1[64][72](4608) | B3[64][72](4608) -> 18432 halves = 36864 B/buf, 3 stages
// gemm2 : A(9216) | B[64][136](8704)                     -> 17920 halves = 35840 B/buf, 3 stages
#define BUFB13 36864
#define B1OFFB 18432
#define B3OFFB 27648
#define BUFB2  35840
#define B2OFFB 18432

extern __shared__ uint32_t dyn[];

// ---------------- gemm13: h = silu(X@w1)*(X@w3). BM=128,BN=64/matrix,KC=64.
// 4 warps (2M x 2N), warp tile 64m x 32n per matrix. 3-stage cp.async pipeline
// with the per-chunk prefetch spread across the 4 ks iterations (anti-MIO-burst).
__global__ __launch_bounds__(128, 2) void gemm13_mma(){
    const int e = blockIdx.z, cnt = g_cnt[e], m0 = blockIdx.y * 128;
    if (m0 >= cnt) return;
    const int n0 = blockIdx.x * 64;

    __shared__ int s_row[128];
    const uint32_t sbase = smem_u32(dyn);
    const int tid = threadIdx.x, wid = tid >> 5, lane = tid & 31;
    const int gq = lane >> 2, tq = lane & 3;
    const int warp_m = (wid & 1) * 64, warp_n = (wid >> 1) * 32;

    s_row[tid] = g_slot_tok[e * T_TOK + min(m0 + tid, cnt - 1)];
    __syncthreads();

    const __half* xs  = g_xh + (size_t)s_row[tid] * D_DIM;            // + kg
    const int brow = tid >> 1, bhw = (tid & 1) * 32;
    const __half* w1s = g_w1h + ((size_t)e * D_DIM + brow) * H_DIM + n0 + bhw;  // + kg*H
    const __half* w3s = g_w3h + ((size_t)e * D_DIM + brow) * H_DIM + n0 + bhw;
    const uint32_t dA  = sbase + (uint32_t)tid * 144u;
    const uint32_t dB1 = sbase + B1OFFB + (uint32_t)(brow * 144 + bhw * 2);
    const uint32_t dB3 = sbase + B3OFFB + (uint32_t)(brow * 144 + bhw * 2);

    auto fill = [&](int c){
        const uint32_t bo = (uint32_t)(c % 3) * BUFB13;
        const int kg = c * KC;
        const __half* pa = xs + kg;
#pragma unroll
        for (int i = 0; i < 8; i++) cpa16(dA + bo + i * 16, pa + i * 8);
        const __half* p1 = w1s + (size_t)kg * H_DIM;
        const __half* p3 = w3s + (size_t)kg * H_DIM;
#pragma unroll
        for (int i = 0; i < 4; i++) cpa16(dB1 + bo + i * 16, p1 + i * 8);
#pragma unroll
        for (int i = 0; i < 4; i++) cpa16(dB3 + bo + i * 16, p3 + i * 8);
    };
    // quarter fill: 2 A-lines + 1 B1-line + 1 B3-line per ks iteration
    auto fill_part = [&](int c, int q){
        const uint32_t bo = (uint32_t)(c % 3) * BUFB13;
        const int kg = c * KC;
        const __half* pa = xs + kg;
        cpa16(dA + bo + (2*q)   * 16, pa + (2*q)   * 8);
        cpa16(dA + bo + (2*q+1) * 16, pa + (2*q+1) * 8);
        const __half* p1 = w1s + (size_t)kg * H_DIM;
        const __half* p3 = w3s + (size_t)kg * H_DIM;
        cpa16(dB1 + bo + q * 16, p1 + q * 8);
        cpa16(dB3 + bo + q * 16, p3 + q * 8);
    };

    // ldmatrix lane offsets (bytes)
    uint32_t a_off[4];
#pragma unroll
    for (int i = 0; i < 4; i++)
        a_off[i] = (uint32_t)(((warp_m + i * 16 + (lane & 15)) * 72 + (lane >> 4) * 8) * 2);
    uint32_t b_off[2];
#pragma unroll
    for (int p = 0; p < 2; p++)
        b_off[p] = (uint32_t)(B1OFFB + ((lane & 15) * 72 + warp_n + p * 16 + (lane >> 4) * 8) * 2);

    float accg[4][4][4], accu[4][4][4];
#pragma unroll
    for (int i = 0; i < 4; i++)
#pragma unroll
        for (int j = 0; j < 4; j++)
#pragma unroll
            for (int q = 0; q < 4; q++) { accg[i][j][q] = 0.f; accu[i][j][q] = 0.f; }

    const int NC = D_DIM / KC;  // 16
    fill(0); CP_COMMIT();
    fill(1); CP_COMMIT();

    for (int c = 0; c < NC; c++) {
        CP_WAIT1();
        __syncthreads();

        const uint32_t abuf = sbase + (uint32_t)(c % 3) * BUFB13;

        uint32_t af[2][4][4], b1f[2][4][2], b3f[2][4][2];
        auto ldfr = [&](int ks, int buf){
#pragma unroll
            for (int i = 0; i < 4; i++) ldsm4(af[buf][i], abuf + a_off[i] + ks * 32);
#pragma unroll
            for (int p = 0; p < 2; p++) {
                uint32_t d[4];
                ldsm4t(d, abuf + b_off[p] + ks * 2304);
                b1f[buf][2*p][0] = d[0]; b1f[buf][2*p][1] = d[1];
                b1f[buf][2*p+1][0] = d[2]; b1f[buf][2*p+1][1] = d[3];
                ldsm4t(d, abuf + b_off[p] + 9216 + ks * 2304);
                b3f[buf][2*p][0] = d[0]; b3f[buf][2*p][1] = d[1];
                b3f[buf][2*p+1][0] = d[2]; b3f[buf][2*p+1][1] = d[3];
            }
        };
        ldfr(0, 0);
        const bool pf = (c + 2 < NC);
#pragma unroll
        for (int ks = 0; ks < 4; ks++) {
            const int cur = ks & 1, nxt = cur ^ 1;
            if (ks < 3) ldfr(ks + 1, nxt);
            if (pf) fill_part(c + 2, ks);   // spread prefetch: 4 cpa per ks
#pragma unroll
            for (int j = 0; j < 4; j++)
#pragma unroll
                for (int i = 0; i < 4; i++) {
                    mma16(accg[i][j], af[cur][i], b1f[cur][j]);
                    mma16(accu[i][j], af[cur][i], b3f[cur][j]);
                }
        }
        CP_COMMIT();  // exactly one group per chunk (legal even with 0 pending ops)
    }

    __half* hb = g_hh + ((size_t)e * T_TOK + m0) * H_DIM + n0;
#pragma unroll
    for (int i = 0; i < 4; i++) {
        const int r0 = warp_m + i * 16 + gq;
        const int r1 = r0 + 8;
#pragma unroll
        for (int j = 0; j < 4; j++) {
            const int col = warp_n + j * 8 + tq * 2;
            if (m0 + r0 < cnt) {
                half2 o = __floats2half2_rn(silu_mul(accg[i][j][0], accu[i][j][0]),
                                            silu_mul(accg[i][j][1], accu[i][j][1]));
                *(half2*)(hb + (size_t)r0 * H_DIM + col) = o;
            }
            if (m0 + r1 < cnt) {
                half2 o = __floats2half2_rn(silu_mul(accg[i][j][2], accu[i][j][2]),
                                            silu_mul(accg[i][j][3], accu[i][j][3]));
                *(half2*)(hb + (size_t)r1 * H_DIM + col) = o;
            }
        }
    }
}

// ---------------- gemm2: out[tok] += w_m * (H @ w2). BM=128,BN=128,KC=64. warp 64x64.
// 3-stage cp.async pipeline, prefetch spread across ks. Fused atomicAdd combine.
__global__ __launch_bounds__(128, 2) void gemm2_mma(float* __restrict__ out){
    const int e = blockIdx.z, cnt = g_cnt[e], m0 = blockIdx.y * 128;
    if (m0 >= cnt) return;
    const int n0 = blockIdx.x * 128;

    const uint32_t sbase = smem_u32(dyn);
    const int tid = threadIdx.x, wid = tid >> 5, lane = tid & 31;
    const int gq = lane >> 2, tq = lane & 3;
    const int warp_m = (wid & 1) * 64, warp_n = (wid >> 1) * 64;

    const __half* hs = g_hh + ((size_t)e * T_TOK + min(m0 + tid, cnt - 1)) * H_DIM;  // + kg
    const int brow = tid >> 1, bhw = (tid & 1) * 64;
    const __half* w2s = g_w2h + ((size_t)e * H_DIM + brow) * D_DIM + n0 + bhw;       // + kg*D
    const uint32_t dA = sbase + (uint32_t)tid * 144u;
    const uint32_t dB = sbase + B2OFFB + (uint32_t)(brow * 272 + bhw * 2);

    auto fill = [&](int c){
        const uint32_t bo = (uint32_t)(c % 3) * BUFB2;
        const int kg = c * KC;
        const __half* pa = hs + kg;
#pragma unroll
        for (int i = 0; i < 8; i++) cpa16(dA + bo + i * 16, pa + i * 8);
        const __half* pb = w2s + (size_t)kg * D_DIM;
#pragma unroll
        for (int i = 0; i < 8; i++) cpa16(dB + bo + i * 16, pb + i * 8);
    };
    auto fill_part = [&](int c, int q){
        const uint32_t bo = (uint32_t)(c % 3) * BUFB2;
        const int kg = c * KC;
        const __half* pa = hs + kg;
        cpa16(dA + bo + (2*q)   * 16, pa + (2*q)   * 8);
        cpa16(dA + bo + (2*q+1) * 16, pa + (2*q+1) * 8);
        const __half* pb = w2s + (size_t)kg * D_DIM;
        cpa16(dB + bo + (2*q)   * 16, pb + (2*q)   * 8);
        cpa16(dB + bo + (2*q+1) * 16, pb + (2*q+1) * 8);
    };

    uint32_t a_off[4];
#pragma unroll
    for (int i = 0; i < 4; i++)
        a_off[i] = (uint32_t)(((warp_m + i * 16 + (lane & 15)) * 72 + (lane >> 4) * 8) * 2);
    uint32_t b_off[4];
#pragma unroll
    for (int p = 0; p < 4; p++)
        b_off[p] = (uint32_t)(B2OFFB + ((lane & 15) * 136 + warp_n + p * 16 + (lane >> 4) * 8) * 2);

    float acc[4][8][4];
#pragma unroll
    for (int i = 0; i < 4; i++)
#pragma unroll
        for (int j = 0; j < 8; j++)
#pragma unroll
            for (int q = 0; q < 4; q++) acc[i][j][q] = 0.f;

    const int NC = H_DIM / KC;  // 44
    fill(0); CP_COMMIT();
    fill(1); CP_COMMIT();

    for (int c = 0; c < NC; c++) {
        CP_WAIT1();
        __syncthreads();

        const uint32_t abuf = sbase + (uint32_t)(c % 3) * BUFB2;
        uint32_t af[2][4][4], bf[2][8][2];

        auto ldfr = [&](int ks, int buf){
#pragma unroll
            for (int i = 0; i < 4; i++) ldsm4(af[buf][i], abuf + a_off[i] + ks * 32);
#pragma unroll
            for (int p = 0; p < 4; p++) {
                uint32_t d[4];
                ldsm4t(d, abuf + b_off[p] + ks * 4352);
                bf[buf][2*p][0] = d[0]; bf[buf][2*p][1] = d[1];
                bf[buf][2*p+1][0] = d[2]; bf[buf][2*p+1][1] = d[3];
            }
        };
        ldfr(0, 0);
        const bool pf = (c + 2 < NC);
#pragma unroll
        for (int ks = 0; ks < 4; ks++) {
            const int cur = ks & 1, nxt = cur ^ 1;
            if (ks < 3) ldfr(ks + 1, nxt);
            if (pf) fill_part(c + 2, ks);
#pragma unroll
            for (int j = 0; j < 8; j++)
#pragma unroll
                for (int i = 0; i < 4; i++) mma16(acc[i][j], af[cur][i], bf[cur][j]);
        }
        CP_COMMIT();
    }

    // fused combine: out[tok, n] += wgt * acc  (RED, no return)
#pragma unroll
    for (int i = 0; i < 4; i++) {
        const int r0 = warp_m + i * 16 + gq;
        const int r1 = r0 + 8;
        if (m0 + r0 < cnt) {
            const int   tok0 = g_slot_tok[e * T_TOK + m0 + r0];
            const float wg0  = g_slot_w  [e * T_TOK + m0 + r0];
            float* o0 = out + (size_t)tok0 * D_DIM + n0;
#pragma unroll
            for (int j = 0; j < 8; j++) {
                const int col = warp_n + j * 8 + tq * 2;
                atomicAdd(o0 + col,     acc[i][j][0] * wg0);
                atomicAdd(o0 + col + 1, acc[i][j][1] * wg0);
            }
        }
        if (m0 + r1 < cnt) {
            const int   tok1 = g_slot_tok[e * T_TOK + m0 + r1];
            const float wg1  = g_slot_w  [e * T_TOK + m0 + r1];
            float* o1 = out + (size_t)tok1 * D_DIM + n0;
#pragma unroll
            for (int j = 0; j < 8; j++) {
                const int col = warp_n + j * 8 + tq * 2;
                atomicAdd(o1 + col,     acc[i][j][2] * wg1);
                atomicAdd(o1 + col + 1, acc[i][j][3] * wg1);
            }
        }
    }
}

// ---------------- launch ----------------
extern "C" void kernel_launch(void* const* d_in, const int* in_sizes, int n_in,
                              void* d_out, int out_size){
    const float* x  = (const float*)d_in[0];
    const float* wg = (const float*)d_in[1];
    const float* w1 = (const float*)d_in[2];
    const float* w2 = (const float*)d_in[3];
    const float* w3 = (const float*)d_in[4];
    float* out = (float*)d_out;

    const int smem13 = 3 * BUFB13;  // 110592
    const int smem2  = 3 * BUFB2;   // 107520
    cudaFuncSetAttribute(gemm13_mma, cudaFuncAttributeMaxDynamicSharedMemorySize, smem13);
    cudaFuncSetAttribute(gemm2_mma,  cudaFuncAttributeMaxDynamicSharedMemorySize, smem2);

    __half* xh;  cudaGetSymbolAddress((void**)&xh,  g_xh);
    __half* w1h; cudaGetSymbolAddress((void**)&w1h, g_w1h);
    __half* w3h; cudaGetSymbolAddress((void**)&w3h, g_w3h);
    __half* w2h; cudaGetSymbolAddress((void**)&w2h, g_w2h);

    const int nw8 = (E_NUM * D_DIM * H_DIM) / 8;
    const int nx8 = (T_TOK * D_DIM) / 8;
    const int ntot = nx8 + 3 * nw8;
    const int nprep = T_TOK + (ntot + 255) / 256;

    zero_cnt_kernel<<<1, 32>>>();
    prep_kernel<<<nprep, 256>>>(x, wg, (float4*)out, w1, w3, w2, xh, w1h, w3h, w2h);
    gemm13_mma<<<dim3(H_DIM / 64, T_TOK / 128, E_NUM), 128, smem13>>>();
    gemm2_mma<<<dim3(D_DIM / 128, T_TOK / 128, E_NUM), 128, smem2>>>(out);
}

// round 17
// speedup vs baseline: 1.6844x; 1.0400x over previous
#include <cuda_runtime.h>
#include <cuda_fp16.h>
#include <math.h>
#include <stdint.h>

#define T_TOK 4096
#define D_DIM 1024
#define E_NUM 8
#define H_DIM 2816
#define KC 64

__device__ int   g_cnt[E_NUM];
__device__ int   g_slot_tok[E_NUM * T_TOK];
__device__ float g_slot_w[E_NUM * T_TOK];
__device__ __half g_xh[(size_t)T_TOK * D_DIM];
__device__ __half g_w1h[(size_t)E_NUM * D_DIM * H_DIM];
__device__ __half g_w3h[(size_t)E_NUM * D_DIM * H_DIM];
__device__ __half g_w2h[(size_t)E_NUM * H_DIM * D_DIM];
__device__ __half g_hh[(size_t)E_NUM * T_TOK * H_DIM];

// ---------------- helpers ----------------
__device__ __forceinline__ uint32_t smem_u32(const void* p){
    uint32_t a; asm("{ .reg .u64 t; cvta.to.shared.u64 t, %1; cvt.u32.u64 %0, t; }" : "=r"(a) : "l"(p)); return a;
}
__device__ __forceinline__ void mma16(float* c, const uint32_t* a, const uint32_t* b){
    asm volatile("mma.sync.aligned.m16n8k16.row.col.f32.f16.f16.f32 "
        "{%0,%1,%2,%3}, {%4,%5,%6,%7}, {%8,%9}, {%0,%1,%2,%3};"
        : "+f"(c[0]), "+f"(c[1]), "+f"(c[2]), "+f"(c[3])
        : "r"(a[0]), "r"(a[1]), "r"(a[2]), "r"(a[3]), "r"(b[0]), "r"(b[1]));
}
__device__ __forceinline__ void ldsm4(uint32_t* r, uint32_t addr){
    asm volatile("ldmatrix.sync.aligned.m8n8.x4.shared.b16 {%0,%1,%2,%3}, [%4];"
        : "=r"(r[0]), "=r"(r[1]), "=r"(r[2]), "=r"(r[3]) : "r"(addr));
}
__device__ __forceinline__ void ldsm4t(uint32_t* r, uint32_t addr){
    asm volatile("ldmatrix.sync.aligned.m8n8.x4.trans.shared.b16 {%0,%1,%2,%3}, [%4];"
        : "=r"(r[0]), "=r"(r[1]), "=r"(r[2]), "=r"(r[3]) : "r"(addr));
}
__device__ __forceinline__ float silu_mul(float g, float u){
    return (g / (1.f + expf(-g))) * u;
}
__device__ __forceinline__ void cpa16(uint32_t dst, const void* src){
    asm volatile("cp.async.cg.shared.global [%0], [%1], 16;" :: "r"(dst), "l"(src) : "memory");
}
#define CP_COMMIT() asm volatile("cp.async.commit_group;" ::: "memory")
#define CP_WAIT1()  asm volatile("cp.async.wait_group 1;" ::: "memory")

// ---------------- small kernels ----------------
__global__ void zero_cnt_kernel() { if (threadIdx.x < E_NUM) g_cnt[threadIdx.x] = 0; }

// fused prep: blocks [0, T_TOK) do gating (+ zero out row); the rest convert
// x/w1/w3/w2 to fp16 (8 elements per thread). The two sections are independent.
__global__ __launch_bounds__(256) void prep_kernel(const float* __restrict__ x,
                                                   const float* __restrict__ wg,
                                                   float4* __restrict__ out,
                                                   const float* __restrict__ w1,
                                                   const float* __restrict__ w3,
                                                   const float* __restrict__ w2,
                                                   __half* __restrict__ xh,
                                                   __half* __restrict__ w1h,
                                                   __half* __restrict__ w3h,
                                                   __half* __restrict__ w2h){
    const int tid = threadIdx.x;
    if (blockIdx.x < T_TOK) {
        __shared__ float s_red[E_NUM][256];
        const int t = blockIdx.x;
        const float* xr = x + (size_t)t * D_DIM;

        out[(size_t)t * (D_DIM / 4) + tid] = make_float4(0.f, 0.f, 0.f, 0.f);

        float part[E_NUM];
#pragma unroll
        for (int e = 0; e < E_NUM; e++) part[e] = 0.f;
        for (int d = tid; d < D_DIM; d += 256) {
            const float xv = xr[d];
            const float* w = wg + (size_t)d * E_NUM;
#pragma unroll
            for (int e = 0; e < E_NUM; e++) part[e] += xv * w[e];
        }
#pragma unroll
        for (int e = 0; e < E_NUM; e++) s_red[e][tid] = part[e];
        __syncthreads();
        for (int s = 128; s > 0; s >>= 1) {
            if (tid < s) {
#pragma unroll
                for (int e = 0; e < E_NUM; e++) s_red[e][tid] += s_red[e][tid + s];
            }
            __syncthreads();
        }
        if (tid == 0) {
            float p[E_NUM]; float mx = -1e30f;
#pragma unroll
            for (int e = 0; e < E_NUM; e++) mx = fmaxf(mx, s_red[e][0]);
#pragma unroll
            for (int e = 0; e < E_NUM; e++) p[e] = expf(s_red[e][0] - mx);
            int i1 = 0;
#pragma unroll
            for (int e = 1; e < E_NUM; e++) if (p[e] > p[i1]) i1 = e;
            int i2 = (i1 == 0) ? 1 : 0;
#pragma unroll
            for (int e = 0; e < E_NUM; e++) if (e != i1 && p[e] > p[i2]) i2 = e;
            const float ws = p[i1] + p[i2];
            const int s0 = atomicAdd(&g_cnt[i1], 1);
            const int s1 = atomicAdd(&g_cnt[i2], 1);
            g_slot_tok[i1 * T_TOK + s0] = t;  g_slot_w[i1 * T_TOK + s0] = p[i1] / ws;
            g_slot_tok[i2 * T_TOK + s1] = t;  g_slot_w[i2 * T_TOK + s1] = p[i2] / ws;
        }
    } else {
        const int nx8 = (T_TOK * D_DIM) / 8;
        const int nw8 = (E_NUM * D_DIM * H_DIM) / 8;
        const int i = (blockIdx.x - T_TOK) * 256 + tid;
        const float* src; __half* dst; size_t off;
        if (i < nx8) { src = x; dst = xh; off = (size_t)i; }
        else {
            const int j = i - nx8;
            const int arr = j / nw8;
            off = (size_t)(j - arr * nw8);
            if (arr == 0)      { src = w1; dst = w1h; }
            else if (arr == 1) { src = w3; dst = w3h; }
            else if (arr == 2) { src = w2; dst = w2h; }
            else return;
        }
        const float4* s4 = (const float4*)src + 2 * off;
        float4 a = s4[0], b = s4[1];
        half2 h0 = __floats2half2_rn(a.x, a.y);
        half2 h1 = __floats2half2_rn(a.z, a.w);
        half2 h2 = __floats2half2_rn(b.x, b.y);
        half2 h3 = __floats2half2_rn(b.z, b.w);
        uint4 o;
        o.x = *(uint32_t*)&h0; o.y = *(uint32_t*)&h1;
        o.z = *(uint32_t*)&h2; o.w = *(uint32_t*)&h3;
        *(uint4*)(dst + 8 * off) = o;
    }
}

// SMEM layouts in halves. A[128][72] rows pitch 144B (bank step 4, conflict-free ldsm).
// gemm13: A(9216) | B1[64][72](4608) | B3[64][72](4608) -> 18432 halves = 36864 B/buf, 3 stages
// gemm2 : A(9216) | B[64][136](8704)                     -> 17920 halves = 35840 B/buf, 3 stages
#define BUFB13 36864
#define B1OFFB 18432
#define B3OFFB 27648
#define BUFB2  35840
#define B2OFFB 18432

extern __shared__ uint32_t dyn[];

// ---------------- gemm13: h = silu(X@w1)*(X@w3). BM=128,BN=64/matrix,KC=64.
// 4 warps (2M x 2N), warp tile 64m x 32n per matrix. 3-stage cp.async pipeline.
// Both the cp.async prefetch AND the next-ks LDSM loads are spread across the
// MMA stream (anti-MIO-burst, validated R16).
__global__ __launch_bounds__(128, 2) void gemm13_mma(){
    const int e = blockIdx.z, cnt = g_cnt[e], m0 = blockIdx.y * 128;
    if (m0 >= cnt) return;
    const int n0 = blockIdx.x * 64;

    __shared__ int s_row[128];
    const uint32_t sbase = smem_u32(dyn);
    const int tid = threadIdx.x, wid = tid >> 5, lane = tid & 31;
    const int gq = lane >> 2, tq = lane & 3;
    const int warp_m = (wid & 1) * 64, warp_n = (wid >> 1) * 32;

    s_row[tid] = g_slot_tok[e * T_TOK + min(m0 + tid, cnt - 1)];
    __syncthreads();

    const __half* xs  = g_xh + (size_t)s_row[tid] * D_DIM;            // + kg
    const int brow = tid >> 1, bhw = (tid & 1) * 32;
    const __half* w1s = g_w1h + ((size_t)e * D_DIM + brow) * H_DIM + n0 + bhw;  // + kg*H
    const __half* w3s = g_w3h + ((size_t)e * D_DIM + brow) * H_DIM + n0 + bhw;
    const uint32_t dA  = sbase + (uint32_t)tid * 144u;
    const uint32_t dB1 = sbase + B1OFFB + (uint32_t)(brow * 144 + bhw * 2);
    const uint32_t dB3 = sbase + B3OFFB + (uint32_t)(brow * 144 + bhw * 2);

    auto fill = [&](int c){
        const uint32_t bo = (uint32_t)(c % 3) * BUFB13;
        const int kg = c * KC;
        const __half* pa = xs + kg;
#pragma unroll
        for (int i = 0; i < 8; i++) cpa16(dA + bo + i * 16, pa + i * 8);
        const __half* p1 = w1s + (size_t)kg * H_DIM;
        const __half* p3 = w3s + (size_t)kg * H_DIM;
#pragma unroll
        for (int i = 0; i < 4; i++) cpa16(dB1 + bo + i * 16, p1 + i * 8);
#pragma unroll
        for (int i = 0; i < 4; i++) cpa16(dB3 + bo + i * 16, p3 + i * 8);
    };
    // quarter fill: 2 A-lines + 1 B1-line + 1 B3-line per ks iteration
    auto fill_part = [&](int c, int q){
        const uint32_t bo = (uint32_t)(c % 3) * BUFB13;
        const int kg = c * KC;
        const __half* pa = xs + kg;
        cpa16(dA + bo + (2*q)   * 16, pa + (2*q)   * 8);
        cpa16(dA + bo + (2*q+1) * 16, pa + (2*q+1) * 8);
        const __half* p1 = w1s + (size_t)kg * H_DIM;
        const __half* p3 = w3s + (size_t)kg * H_DIM;
        cpa16(dB1 + bo + q * 16, p1 + q * 8);
        cpa16(dB3 + bo + q * 16, p3 + q * 8);
    };

    // ldmatrix lane offsets (bytes)
    uint32_t a_off[4];
#pragma unroll
    for (int i = 0; i < 4; i++)
        a_off[i] = (uint32_t)(((warp_m + i * 16 + (lane & 15)) * 72 + (lane >> 4) * 8) * 2);
    uint32_t b_off[2];
#pragma unroll
    for (int p = 0; p < 2; p++)
        b_off[p] = (uint32_t)(B1OFFB + ((lane & 15) * 72 + warp_n + p * 16 + (lane >> 4) * 8) * 2);

    float accg[4][4][4], accu[4][4][4];
#pragma unroll
    for (int i = 0; i < 4; i++)
#pragma unroll
        for (int j = 0; j < 4; j++)
#pragma unroll
            for (int q = 0; q < 4; q++) { accg[i][j][q] = 0.f; accu[i][j][q] = 0.f; }

    const int NC = D_DIM / KC;  // 16
    fill(0); CP_COMMIT();
    fill(1); CP_COMMIT();

    for (int c = 0; c < NC; c++) {
        CP_WAIT1();
        __syncthreads();

        const uint32_t abuf = sbase + (uint32_t)(c % 3) * BUFB13;

        uint32_t af[2][4][4], b1f[2][4][2], b3f[2][4][2];
        // chunk-entry fragments (no alternative: needed immediately)
#pragma unroll
        for (int i = 0; i < 4; i++) ldsm4(af[0][i], abuf + a_off[i]);
#pragma unroll
        for (int p = 0; p < 2; p++) {
            uint32_t d[4];
            ldsm4t(d, abuf + b_off[p]);
            b1f[0][2*p][0] = d[0]; b1f[0][2*p][1] = d[1];
            b1f[0][2*p+1][0] = d[2]; b1f[0][2*p+1][1] = d[3];
            ldsm4t(d, abuf + b_off[p] + 9216);
            b3f[0][2*p][0] = d[0]; b3f[0][2*p][1] = d[1];
            b3f[0][2*p+1][0] = d[2]; b3f[0][2*p+1][1] = d[3];
        }
        const bool pf = (c + 2 < NC);
#pragma unroll
        for (int ks = 0; ks < 4; ks++) {
            const int cur = ks & 1, nxt = cur ^ 1;
            const int k1 = ks + 1;
            const bool ld = (ks < 3);
            if (pf) fill_part(c + 2, ks);   // spread prefetch: 4 cpa per ks
#pragma unroll
            for (int j = 0; j < 4; j++) {
                if (ld) {
                    // spread next-ks fragment loads: 1 A-ldsm + 1 B-ldsm per j
                    ldsm4(af[nxt][j], abuf + a_off[j] + k1 * 32);
                    uint32_t d[4];
                    const int p = j >> 1;
                    if ((j & 1) == 0) {
                        ldsm4t(d, abuf + b_off[p] + k1 * 2304);
                        b1f[nxt][2*p][0] = d[0]; b1f[nxt][2*p][1] = d[1];
                        b1f[nxt][2*p+1][0] = d[2]; b1f[nxt][2*p+1][1] = d[3];
                    } else {
                        ldsm4t(d, abuf + b_off[p] + 9216 + k1 * 2304);
                        b3f[nxt][2*p][0] = d[0]; b3f[nxt][2*p][1] = d[1];
                        b3f[nxt][2*p+1][0] = d[2]; b3f[nxt][2*p+1][1] = d[3];
                    }
                }
#pragma unroll
                for (int i = 0; i < 4; i++) {
                    mma16(accg[i][j], af[cur][i], b1f[cur][j]);
                    mma16(accu[i][j], af[cur][i], b3f[cur][j]);
                }
            }
        }
        CP_COMMIT();  // exactly one group per chunk
    }

    __half* hb = g_hh + ((size_t)e * T_TOK + m0) * H_DIM + n0;
#pragma unroll
    for (int i = 0; i < 4; i++) {
        const int r0 = warp_m + i * 16 + gq;
        const int r1 = r0 + 8;
#pragma unroll
        for (int j = 0; j < 4; j++) {
            const int col = warp_n + j * 8 + tq * 2;
            if (m0 + r0 < cnt) {
                half2 o = __floats2half2_rn(silu_mul(accg[i][j][0], accu[i][j][0]),
                                            silu_mul(accg[i][j][1], accu[i][j][1]));
                *(half2*)(hb + (size_t)r0 * H_DIM + col) = o;
            }
            if (m0 + r1 < cnt) {
                half2 o = __floats2half2_rn(silu_mul(accg[i][j][2], accu[i][j][2]),
                                            silu_mul(accg[i][j][3], accu[i][j][3]));
                *(half2*)(hb + (size_t)r1 * H_DIM + col) = o;
            }
        }
    }
}

// ---------------- gemm2: out[tok] += w_m * (H @ w2). BM=128,BN=128,KC=64. warp 64x64.
// 3-stage cp.async pipeline; prefetch AND next-ks LDSM spread across the MMA stream.
__global__ __launch_bounds__(128, 2) void gemm2_mma(float* __restrict__ out){
    const int e = blockIdx.z, cnt = g_cnt[e], m0 = blockIdx.y * 128;
    if (m0 >= cnt) return;
    const int n0 = blockIdx.x * 128;

    const uint32_t sbase = smem_u32(dyn);
    const int tid = threadIdx.x, wid = tid >> 5, lane = tid & 31;
    const int gq = lane >> 2, tq = lane & 3;
    const int warp_m = (wid & 1) * 64, warp_n = (wid >> 1) * 64;

    const __half* hs = g_hh + ((size_t)e * T_TOK + min(m0 + tid, cnt - 1)) * H_DIM;  // + kg
    const int brow = tid >> 1, bhw = (tid & 1) * 64;
    const __half* w2s = g_w2h + ((size_t)e * H_DIM + brow) * D_DIM + n0 + bhw;       // + kg*D
    const uint32_t dA = sbase + (uint32_t)tid * 144u;
    const uint32_t dB = sbase + B2OFFB + (uint32_t)(brow * 272 + bhw * 2);

    auto fill = [&](int c){
        const uint32_t bo = (uint32_t)(c % 3) * BUFB2;
        const int kg = c * KC;
        const __half* pa = hs + kg;
#pragma unroll
        for (int i = 0; i < 8; i++) cpa16(dA + bo + i * 16, pa + i * 8);
        const __half* pb = w2s + (size_t)kg * D_DIM;
#pragma unroll
        for (int i = 0; i < 8; i++) cpa16(dB + bo + i * 16, pb + i * 8);
    };
    auto fill_part = [&](int c, int q){
        const uint32_t bo = (uint32_t)(c % 3) * BUFB2;
        const int kg = c * KC;
        const __half* pa = hs + kg;
        cpa16(dA + bo + (2*q)   * 16, pa + (2*q)   * 8);
        cpa16(dA + bo + (2*q+1) * 16, pa + (2*q+1) * 8);
        const __half* pb = w2s + (size_t)kg * D_DIM;
        cpa16(dB + bo + (2*q)   * 16, pb + (2*q)   * 8);
        cpa16(dB + bo + (2*q+1) * 16, pb + (2*q+1) * 8);
    };

    uint32_t a_off[4];
#pragma unroll
    for (int i = 0; i < 4; i++)
        a_off[i] = (uint32_t)(((warp_m + i * 16 + (lane & 15)) * 72 + (lane >> 4) * 8) * 2);
    uint32_t b_off[4];
#pragma unroll
    for (int p = 0; p < 4; p++)
        b_off[p] = (uint32_t)(B2OFFB + ((lane & 15) * 136 + warp_n + p * 16 + (lane >> 4) * 8) * 2);

    float acc[4][8][4];
#pragma unroll
    for (int i = 0; i < 4; i++)
#pragma unroll
        for (int j = 0; j < 8; j++)
#pragma unroll
            for (int q = 0; q < 4; q++) acc[i][j][q] = 0.f;

    const int NC = H_DIM / KC;  // 44
    fill(0); CP_COMMIT();
    fill(1); CP_COMMIT();

    for (int c = 0; c < NC; c++) {
        CP_WAIT1();
        __syncthreads();

        const uint32_t abuf = sbase + (uint32_t)(c % 3) * BUFB2;
        uint32_t af[2][4][4], bf[2][8][2];

        // chunk-entry fragments
#pragma unroll
        for (int i = 0; i < 4; i++) ldsm4(af[0][i], abuf + a_off[i]);
#pragma unroll
        for (int p = 0; p < 4; p++) {
            uint32_t d[4];
            ldsm4t(d, abuf + b_off[p]);
            bf[0][2*p][0] = d[0]; bf[0][2*p][1] = d[1];
            bf[0][2*p+1][0] = d[2]; bf[0][2*p+1][1] = d[3];
        }
        const bool pf = (c + 2 < NC);
#pragma unroll
        for (int ks = 0; ks < 4; ks++) {
            const int cur = ks & 1, nxt = cur ^ 1;
            const int k1 = ks + 1;
            const bool ld = (ks < 3);
            if (pf) fill_part(c + 2, ks);
#pragma unroll
            for (int j = 0; j < 8; j++) {
                if (ld) {
                    // spread next-ks fragment loads: one LDSM per j
                    if (j < 4) {
                        ldsm4(af[nxt][j], abuf + a_off[j] + k1 * 32);
                    } else {
                        const int p = j - 4;
                        uint32_t d[4];
                        ldsm4t(d, abuf + b_off[p] + k1 * 4352);
                        bf[nxt][2*p][0] = d[0]; bf[nxt][2*p][1] = d[1];
                        bf[nxt][2*p+1][0] = d[2]; bf[nxt][2*p+1][1] = d[3];
                    }
                }
#pragma unroll
                for (int i = 0; i < 4; i++) mma16(acc[i][j], af[cur][i], bf[cur][j]);
            }
        }
        CP_COMMIT();
    }

    // fused combine: out[tok, n] += wgt * acc  (RED, no return)
#pragma unroll
    for (int i = 0; i < 4; i++) {
        const int r0 = warp_m + i * 16 + gq;
        const int r1 = r0 + 8;
        if (m0 + r0 < cnt) {
            const int   tok0 = g_slot_tok[e * T_TOK + m0 + r0];
            const float wg0  = g_slot_w  [e * T_TOK + m0 + r0];
            float* o0 = out + (size_t)tok0 * D_DIM + n0;
#pragma unroll
            for (int j = 0; j < 8; j++) {
                const int col = warp_n + j * 8 + tq * 2;
                atomicAdd(o0 + col,     acc[i][j][0] * wg0);
                atomicAdd(o0 + col + 1, acc[i][j][1] * wg0);
            }
        }
        if (m0 + r1 < cnt) {
            const int   tok1 = g_slot_tok[e * T_TOK + m0 + r1];
            const float wg1  = g_slot_w  [e * T_TOK + m0 + r1];
            float* o1 = out + (size_t)tok1 * D_DIM + n0;
#pragma unroll
            for (int j = 0; j < 8; j++) {
                const int col = warp_n + j * 8 + tq * 2;
                atomicAdd(o1 + col,     acc[i][j][2] * wg1);
                atomicAdd(o1 + col + 1, acc[i][j][3] * wg1);
            }
        }
    }
}

// ---------------- launch ----------------
extern "C" void kernel_launch(void* const* d_in, const int* in_sizes, int n_in,
                              void* d_out, int out_size){
    const float* x  = (const float*)d_in[0];
    const float* wg = (const float*)d_in[1];
    const float* w1 = (const float*)d_in[2];
    const float* w2 = (const float*)d_in[3];
    const float* w3 = (const float*)d_in[4];
    float* out = (float*)d_out;

    const int smem13 = 3 * BUFB13;  // 110592
    const int smem2  = 3 * BUFB2;   // 107520
    cudaFuncSetAttribute(gemm13_mma, cudaFuncAttributeMaxDynamicSharedMemorySize, smem13);
    cudaFuncSetAttribute(gemm2_mma,  cudaFuncAttributeMaxDynamicSharedMemorySize, smem2);

    __half* xh;  cudaGetSymbolAddress((void**)&xh,  g_xh);
    __half* w1h; cudaGetSymbolAddress((void**)&w1h, g_w1h);
    __half* w3h; cudaGetSymbolAddress((void**)&w3h, g_w3h);
    __half* w2h; cudaGetSymbolAddress((void**)&w2h, g_w2h);

    const int nw8 = (E_NUM * D_DIM * H_DIM) / 8;
    const int nx8 = (T_TOK * D_DIM) / 8;
    const int ntot = nx8 + 3 * nw8;
    const int nprep = T_TOK + (ntot + 255) / 256;

    zero_cnt_kernel<<<1, 32>>>();
    prep_kernel<<<nprep, 256>>>(x, wg, (float4*)out, w1, w3, w2, xh, w1h, w3h, w2h);
    gemm13_mma<<<dim3(H_DIM / 64, T_TOK / 128, E_NUM), 128, smem13>>>();
    gemm2_mma<<<dim3(D_DIM / 128, T_TOK / 128, E_NUM), 128, smem2>>>(out);
}